// round 1
// baseline (speedup 1.0000x reference)
#include <cuda_runtime.h>

#define BSZ 2
#define NH 16
#define SEQ 2048
#define DM 1024
#define HD 64
#define BH (BSZ*NH)

// Scratch (device globals — no allocations allowed)
__device__ float g_q[BH * SEQ * HD];
__device__ float g_k[BH * SEQ * HD];
__device__ float g_v[BH * SEQ * HD];
__device__ float g_rowsum[BH * SEQ];

// ---------------------------------------------------------------------------
// Kernel 1: QKV projection. C[r][c] = sum_k x[r][k] * W[c][k] + b[c]
// Written head-split: out[((b*NH+h)*SEQ+s)*HD + d]
// Tiles: 64x64 output, 16 K-slab, 256 threads, 4x4 micro-tile.
// Smem K-major [k][r] with XOR swizzle (groups of 4 rows) -> float4 reads.
// ---------------------------------------------------------------------------
__global__ __launch_bounds__(256) void qkv_gemm_kernel(
    const float* __restrict__ x,
    const float* __restrict__ wq, const float* __restrict__ bq,
    const float* __restrict__ wk, const float* __restrict__ bk,
    const float* __restrict__ wv, const float* __restrict__ bv)
{
    __shared__ float As[16][64];
    __shared__ float Bs[16][64];

    const int z = blockIdx.z;
    const float* W    = (z == 0) ? wq : (z == 1) ? wk : wv;
    const float* bvec = (z == 0) ? bq : (z == 1) ? bk : bv;
    float* outp       = (z == 0) ? g_q : (z == 1) ? g_k : g_v;

    const int tid = threadIdx.x;
    const int tx = tid & 15, ty = tid >> 4;
    const int row0 = blockIdx.y << 6;
    const int col0 = blockIdx.x << 6;

    const int lr = tid >> 2;          // 0..63 row within tile
    const int lk = (tid & 3) << 2;    // 0,4,8,12 k within slab
    const int lrs = lr ^ lk;          // swizzled column (lk == (k>>2)<<2 for k=lk..lk+3)

    float acc[4][4] = {};

    const float* xg = x + (size_t)(row0 + lr) * DM + lk;
    const float* wg = W + (size_t)(col0 + lr) * DM + lk;

    for (int k0 = 0; k0 < DM; k0 += 16) {
        float4 a4 = *(const float4*)(xg + k0);
        float4 b4 = *(const float4*)(wg + k0);
        __syncthreads();
        As[lk+0][lrs] = a4.x; As[lk+1][lrs] = a4.y; As[lk+2][lrs] = a4.z; As[lk+3][lrs] = a4.w;
        Bs[lk+0][lrs] = b4.x; Bs[lk+1][lrs] = b4.y; Bs[lk+2][lrs] = b4.z; Bs[lk+3][lrs] = b4.w;
        __syncthreads();
        #pragma unroll
        for (int k = 0; k < 16; k++) {
            const int t4 = (k >> 2) << 2;
            float4 av = *(const float4*)&As[k][(ty << 2) ^ t4];
            float4 bb = *(const float4*)&Bs[k][(tx << 2) ^ t4];
            const float* aa = &av.x;
            const float* bx = &bb.x;
            #pragma unroll
            for (int i = 0; i < 4; i++)
                #pragma unroll
                for (int j = 0; j < 4; j++)
                    acc[i][j] += aa[i] * bx[j];
        }
    }

    const int h = col0 >> 6;  // 64-wide col tile == exactly one head
    #pragma unroll
    for (int i = 0; i < 4; i++) {
        int r = row0 + (ty << 2) + i;
        int b = r >> 11;          // /SEQ
        int s = r & (SEQ - 1);
        float4 o;
        o.x = acc[i][0] + bvec[col0 + (tx << 2) + 0];
        o.y = acc[i][1] + bvec[col0 + (tx << 2) + 1];
        o.z = acc[i][2] + bvec[col0 + (tx << 2) + 2];
        o.w = acc[i][3] + bvec[col0 + (tx << 2) + 3];
        *(float4*)&outp[(((size_t)b * NH + h) * SEQ + s) * HD + (tx << 2)] = o;
    }
}

// ---------------------------------------------------------------------------
// Kernel 2: fused attention. Per block: one (bh, 64-row q-tile).
// Loops over 64-col k-tiles: S = Q K^T * scale + bias; masked -> 0 else exp;
// writes unnormalized P to attn, accumulates rowsum and P@V; at end writes
// out = acc/rowsum and rowsum to g_rowsum (normalize pass fixes attn).
// Smem: Qs/Ks transposed [d][row] with XOR swizzle; Vs [k][d]; Ps [q][k].
// 64 KB dynamic smem (opt-in via cudaFuncSetAttribute).
// ---------------------------------------------------------------------------
#define ATTN_SMEM_BYTES (4 * 64 * 64 * 4)

__global__ __launch_bounds__(256) void attn_kernel(
    const float* __restrict__ bias,
    const int*   __restrict__ mask,
    float* __restrict__ outp,
    float* __restrict__ attn)
{
    extern __shared__ float sm[];
    float (*Qs)[64] = (float(*)[64])(sm);          // [d][q] swizzled
    float (*Ks)[64] = (float(*)[64])(sm + 4096);   // [d][k] swizzled
    float (*Vs)[64] = (float(*)[64])(sm + 8192);   // [k][d]
    float (*Ps)[64] = (float(*)[64])(sm + 12288);  // [q][k]

    const int tid = threadIdx.x;
    const int tx = tid & 15, ty = tid >> 4;
    const int qt = blockIdx.x;
    const int bh = blockIdx.y;
    const int h  = bh & (NH - 1);
    const int q0 = qt << 6;
    const float scale = 0.125f;  // 1/sqrt(64)

    // Load Q tile, transposed + swizzled
    const float* Qg = g_q + ((size_t)bh * SEQ + q0) * HD;
    #pragma unroll
    for (int it = 0; it < 4; it++) {
        int idx = tid + it * 256;
        int r  = idx >> 4;
        int d4 = (idx & 15) << 2;
        float4 v = *(const float4*)&Qg[r * HD + d4];
        int rs = r ^ d4;
        Qs[d4+0][rs] = v.x; Qs[d4+1][rs] = v.y; Qs[d4+2][rs] = v.z; Qs[d4+3][rs] = v.w;
    }

    float oacc[4][4] = {};
    float rsum[4] = {};

    for (int kt = 0; kt < SEQ / 64; kt++) {
        const int k0 = kt << 6;
        const float* Kg = g_k + ((size_t)bh * SEQ + k0) * HD;
        const float* Vg = g_v + ((size_t)bh * SEQ + k0) * HD;

        __syncthreads();   // protect Ks/Vs/Ps from previous iteration
        #pragma unroll
        for (int it = 0; it < 4; it++) {
            int idx = tid + it * 256;
            int r  = idx >> 4;
            int d4 = (idx & 15) << 2;
            float4 kv = *(const float4*)&Kg[r * HD + d4];
            int rs = r ^ d4;
            Ks[d4+0][rs] = kv.x; Ks[d4+1][rs] = kv.y; Ks[d4+2][rs] = kv.z; Ks[d4+3][rs] = kv.w;
            float4 vv = *(const float4*)&Vg[r * HD + d4];
            *(float4*)&Vs[r][d4] = vv;
        }
        __syncthreads();

        // S = Q K^T (4x4 micro-tile per thread)
        float s[4][4] = {};
        #pragma unroll 16
        for (int d = 0; d < 64; d++) {
            const int t4 = (d >> 2) << 2;
            float4 qv = *(const float4*)&Qs[d][(ty << 2) ^ t4];
            float4 kv = *(const float4*)&Ks[d][(tx << 2) ^ t4];
            const float* qa = &qv.x;
            const float* ka = &kv.x;
            #pragma unroll
            for (int i = 0; i < 4; i++)
                #pragma unroll
                for (int j = 0; j < 4; j++)
                    s[i][j] += qa[i] * ka[j];
        }

        // epilogue: bias + mask + exp, write unnormalized attn, stage P
        #pragma unroll
        for (int i = 0; i < 4; i++) {
            const int qg = q0 + (ty << 2) + i;
            const int kc = k0 + (tx << 2);
            float4 b4 = *(const float4*)&bias[((size_t)h * SEQ + qg) * SEQ + kc];
            int4  m4 = *(const int4*)&mask[(size_t)qg * SEQ + kc];
            float4 p;
            p.x = m4.x ? __expf(fmaf(s[i][0], scale, b4.x)) : 0.0f;
            p.y = m4.y ? __expf(fmaf(s[i][1], scale, b4.y)) : 0.0f;
            p.z = m4.z ? __expf(fmaf(s[i][2], scale, b4.z)) : 0.0f;
            p.w = m4.w ? __expf(fmaf(s[i][3], scale, b4.w)) : 0.0f;
            rsum[i] += (p.x + p.y) + (p.z + p.w);
            *(float4*)&attn[((size_t)bh * SEQ + qg) * SEQ + kc] = p;
            *(float4*)&Ps[(ty << 2) + i][tx << 2] = p;
        }
        __syncthreads();

        // P @ V accumulate
        #pragma unroll 16
        for (int k = 0; k < 64; k++) {
            float4 vv = *(const float4*)&Vs[k][tx << 2];
            float p0 = Ps[(ty << 2) + 0][k];
            float p1 = Ps[(ty << 2) + 1][k];
            float p2 = Ps[(ty << 2) + 2][k];
            float p3 = Ps[(ty << 2) + 3][k];
            const float* va = &vv.x;
            #pragma unroll
            for (int j = 0; j < 4; j++) {
                oacc[0][j] += p0 * va[j];
                oacc[1][j] += p1 * va[j];
                oacc[2][j] += p2 * va[j];
                oacc[3][j] += p3 * va[j];
            }
        }
    }

    // rowsum reduction across tx (reuse Ps)
    __syncthreads();
    #pragma unroll
    for (int i = 0; i < 4; i++) Ps[(ty << 2) + i][tx] = rsum[i];
    __syncthreads();
    if (tid < 64) {
        float ssum = 0.0f;
        #pragma unroll
        for (int t = 0; t < 16; t++) ssum += Ps[tid][t];
        g_rowsum[(size_t)bh * SEQ + q0 + tid] = ssum;
        Qs[0][tid] = 1.0f / ssum;   // Qs free now; row 0 used as inv broadcast
    }
    __syncthreads();

    #pragma unroll
    for (int i = 0; i < 4; i++) {
        const float inv = Qs[0][(ty << 2) + i];
        float4 o = make_float4(oacc[i][0] * inv, oacc[i][1] * inv,
                               oacc[i][2] * inv, oacc[i][3] * inv);
        *(float4*)&outp[((size_t)bh * SEQ + q0 + (ty << 2) + i) * HD + (tx << 2)] = o;
    }
}

// ---------------------------------------------------------------------------
// Kernel 3: normalize attention weights by rowsum. One block per row.
// ---------------------------------------------------------------------------
__global__ __launch_bounds__(512) void norm_kernel(float* __restrict__ attn)
{
    const size_t row = blockIdx.x;
    const float inv = 1.0f / g_rowsum[row];
    float4* p = (float4*)(attn + row * SEQ);
    float4 v = p[threadIdx.x];
    v.x *= inv; v.y *= inv; v.z *= inv; v.w *= inv;
    p[threadIdx.x] = v;
}

// ---------------------------------------------------------------------------
extern "C" void kernel_launch(void* const* d_in, const int* in_sizes, int n_in,
                              void* d_out, int out_size)
{
    const float* x    = (const float*)d_in[0];
    const float* bias = (const float*)d_in[1];
    const int*   mask = (const int*)d_in[2];
    const float* wq   = (const float*)d_in[3];
    const float* bq   = (const float*)d_in[4];
    const float* wk   = (const float*)d_in[5];
    const float* bk   = (const float*)d_in[6];
    const float* wv   = (const float*)d_in[7];
    const float* bv   = (const float*)d_in[8];

    float* outp = (float*)d_out;                       // [2,16,2048,64]
    float* attn = outp + (size_t)BH * SEQ * HD;        // [2,16,2048,2048]

    // opt-in to 64KB dynamic smem (idempotent, capture-safe: not a stream op)
    cudaFuncSetAttribute(attn_kernel,
                         cudaFuncAttributeMaxDynamicSharedMemorySize,
                         ATTN_SMEM_BYTES);

    // 1) QKV projections
    qkv_gemm_kernel<<<dim3(DM / 64, (BSZ * SEQ) / 64, 3), 256>>>(
        x, wq, bq, wk, bk, wv, bv);

    // 2) fused attention (unnormalized weights + normalized output)
    attn_kernel<<<dim3(SEQ / 64, BH), 256, ATTN_SMEM_BYTES>>>(
        bias, mask, outp, attn);

    // 3) normalize attention weights
    norm_kernel<<<dim3(BH * SEQ), 512>>>(attn);
}

// round 2
// speedup vs baseline: 1.0011x; 1.0011x over previous
#include <cuda_runtime.h>

#define BSZ 2
#define NH 16
#define SEQ 2048
#define DM 1024
#define HD 64
#define BH (BSZ*NH)

// Scratch (device globals — no allocations allowed)
__device__ float g_q[BH * SEQ * HD];
__device__ float g_k[BH * SEQ * HD];
__device__ float g_v[BH * SEQ * HD];
__device__ float g_rowsum[BH * SEQ];

// ---------------------------------------------------------------------------
// Kernel 1: QKV projection. C[r][c] = sum_k x[r][k] * W[c][k] + b[c]
// 128x128 tile, K-slab 8, 256 threads, 8x8 micro-tile, double-buffered smem.
// Smem K-major [k][row] with XOR-by-(k&4) swizzle for conflict-free float4.
// ---------------------------------------------------------------------------
__global__ __launch_bounds__(256, 2) void qkv_gemm_kernel(
    const float* __restrict__ x,
    const float* __restrict__ wq, const float* __restrict__ bq,
    const float* __restrict__ wk, const float* __restrict__ bk,
    const float* __restrict__ wv, const float* __restrict__ bv)
{
    __shared__ float As[2][8][128];
    __shared__ float Bs[2][8][128];

    const int z = blockIdx.z;
    const float* W    = (z == 0) ? wq : (z == 1) ? wk : wv;
    const float* bvec = (z == 0) ? bq : (z == 1) ? bk : bv;
    float* outp       = (z == 0) ? g_q : (z == 1) ? g_k : g_v;

    const int tid = threadIdx.x;
    const int tx = tid & 15, ty = tid >> 4;
    const int row0 = blockIdx.y << 7;
    const int col0 = blockIdx.x << 7;

    const int lr = tid >> 1;          // 0..127
    const int lk = (tid & 1) << 2;    // 0 or 4
    const int lc = lr ^ lk;           // swizzled store column

    const float* xg = x + (size_t)(row0 + lr) * DM + lk;
    const float* wg = W + (size_t)(col0 + lr) * DM + lk;

    float acc[8][8] = {};

    float4 a = *(const float4*)xg;
    float4 b = *(const float4*)wg;
    #pragma unroll
    for (int j = 0; j < 4; j++) {
        As[0][lk + j][lc] = (&a.x)[j];
        Bs[0][lk + j][lc] = (&b.x)[j];
    }

    const int NIT = DM / 8;
    for (int it = 0; it < NIT; it++) {
        __syncthreads();
        const int buf = it & 1;
        if (it + 1 < NIT) {
            a = *(const float4*)(xg + (size_t)(it + 1) * 8);
            b = *(const float4*)(wg + (size_t)(it + 1) * 8);
        }
        #pragma unroll
        for (int k = 0; k < 8; k++) {
            const int s4 = k & 4;
            float4 a0 = *(const float4*)&As[buf][k][(ty << 2) ^ s4];
            float4 a1 = *(const float4*)&As[buf][k][((ty << 2) + 64) ^ s4];
            float4 b0 = *(const float4*)&Bs[buf][k][(tx << 2) ^ s4];
            float4 b1 = *(const float4*)&Bs[buf][k][((tx << 2) + 64) ^ s4];
            float qa[8] = {a0.x, a0.y, a0.z, a0.w, a1.x, a1.y, a1.z, a1.w};
            float kb[8] = {b0.x, b0.y, b0.z, b0.w, b1.x, b1.y, b1.z, b1.w};
            #pragma unroll
            for (int i = 0; i < 8; i++)
                #pragma unroll
                for (int j = 0; j < 8; j++)
                    acc[i][j] = fmaf(qa[i], kb[j], acc[i][j]);
        }
        if (it + 1 < NIT) {
            #pragma unroll
            for (int j = 0; j < 4; j++) {
                As[buf ^ 1][lk + j][lc] = (&a.x)[j];
                Bs[buf ^ 1][lk + j][lc] = (&b.x)[j];
            }
        }
    }

    #pragma unroll
    for (int m = 0; m < 8; m++) {
        const int rl = (ty << 2) + ((m >> 2) << 6) + (m & 3);
        const int r = row0 + rl;
        const int bb = r >> 11;          // / SEQ
        const int ss = r & (SEQ - 1);
        #pragma unroll
        for (int cg = 0; cg < 2; cg++) {
            const int c = col0 + (tx << 2) + (cg << 6);
            const int h = c >> 6;
            const int d = c & 63;
            float4 o;
            o.x = acc[m][cg * 4 + 0] + bvec[c + 0];
            o.y = acc[m][cg * 4 + 1] + bvec[c + 1];
            o.z = acc[m][cg * 4 + 2] + bvec[c + 2];
            o.w = acc[m][cg * 4 + 3] + bvec[c + 3];
            *(float4*)&outp[(((size_t)bb * NH + h) * SEQ + ss) * HD + d] = o;
        }
    }
}

// ---------------------------------------------------------------------------
// Kernel 2: fused attention. Per block: (bh, 128-row q-tile), loop 128-col
// k-tiles. S = QK^T*scale + bias; masked->0 else exp; write unnormalized attn,
// accumulate rowsum + P@V; epilogue writes out = acc/rowsum, rowsum to global.
// Smem: Qs/Ks [d][row] swizzled; Vs [k][d]; Ps [q][k]. 160 KB dynamic.
// ---------------------------------------------------------------------------
#define ATTN_SMEM_BYTES ((64*128 + 64*128 + 128*64 + 128*128) * 4)

__global__ __launch_bounds__(256, 1) void attn_kernel(
    const float* __restrict__ bias,
    const int*   __restrict__ mask,
    float* __restrict__ outp,
    float* __restrict__ attn)
{
    extern __shared__ float sm[];
    float (*Qs)[128] = (float(*)[128])(sm);            // [64 d][128 q] swizzled
    float (*Ks)[128] = (float(*)[128])(sm + 8192);     // [64 d][128 k] swizzled
    float (*Vs)[64]  = (float(*)[64]) (sm + 16384);    // [128 k][64 d]
    float (*Ps)[128] = (float(*)[128])(sm + 24576);    // [128 q][128 k]

    const int tid = threadIdx.x;
    const int tx = tid & 15, ty = tid >> 4;
    const int bh = blockIdx.y;
    const int h  = bh & (NH - 1);
    const int q0 = blockIdx.x << 7;
    const float scale = 0.125f;  // 1/sqrt(64)

    // Load Q tile (128 x 64), transposed + swizzled
    const float* Qg = g_q + ((size_t)bh * SEQ + q0) * HD;
    #pragma unroll
    for (int it = 0; it < 8; it++) {
        int idx = tid + it * 256;       // 0..2047
        int r  = idx >> 4;              // 0..127
        int d4 = (idx & 15) << 2;       // 0..60
        float4 v = *(const float4*)&Qg[r * HD + d4];
        int cs = r ^ d4;
        Qs[d4+0][cs] = v.x; Qs[d4+1][cs] = v.y;
        Qs[d4+2][cs] = v.z; Qs[d4+3][cs] = v.w;
    }

    float oacc[8][4] = {};
    float rsum[8] = {};

    for (int kt = 0; kt < SEQ / 128; kt++) {
        const int k0 = kt << 7;
        const float* Kg = g_k + ((size_t)bh * SEQ + k0) * HD;
        const float* Vg = g_v + ((size_t)bh * SEQ + k0) * HD;

        __syncthreads();   // previous PV done before overwriting Ks/Vs
        #pragma unroll
        for (int it = 0; it < 8; it++) {
            int idx = tid + it * 256;
            int r  = idx >> 4;
            int d4 = (idx & 15) << 2;
            float4 kv = *(const float4*)&Kg[r * HD + d4];
            int cs = r ^ d4;
            Ks[d4+0][cs] = kv.x; Ks[d4+1][cs] = kv.y;
            Ks[d4+2][cs] = kv.z; Ks[d4+3][cs] = kv.w;
            float4 vv = *(const float4*)&Vg[r * HD + d4];
            *(float4*)&Vs[r][d4] = vv;
        }
        __syncthreads();

        // S = Q K^T  (8x8 micro-tile)
        float s[8][8] = {};
        #pragma unroll 8
        for (int d = 0; d < 64; d++) {
            const int s4 = d & 60;
            float4 q0v = *(const float4*)&Qs[d][(ty << 2) ^ s4];
            float4 q1v = *(const float4*)&Qs[d][((ty << 2) + 64) ^ s4];
            float4 k0v = *(const float4*)&Ks[d][(tx << 2) ^ s4];
            float4 k1v = *(const float4*)&Ks[d][((tx << 2) + 64) ^ s4];
            float qa[8] = {q0v.x, q0v.y, q0v.z, q0v.w, q1v.x, q1v.y, q1v.z, q1v.w};
            float kb[8] = {k0v.x, k0v.y, k0v.z, k0v.w, k1v.x, k1v.y, k1v.z, k1v.w};
            #pragma unroll
            for (int i = 0; i < 8; i++)
                #pragma unroll
                for (int j = 0; j < 8; j++)
                    s[i][j] = fmaf(qa[i], kb[j], s[i][j]);
        }

        // epilogue: bias + mask + exp; store unnormalized attn; stage P
        #pragma unroll
        for (int m = 0; m < 8; m++) {
            const int rl = (ty << 2) + ((m >> 2) << 6) + (m & 3);
            const int qg = q0 + rl;
            const float* brow = bias + ((size_t)h * SEQ + qg) * SEQ + k0;
            const int*   mrow = mask + (size_t)qg * SEQ + k0;
            float*       arow = attn + ((size_t)bh * SEQ + qg) * SEQ + k0;
            #pragma unroll
            for (int cg = 0; cg < 2; cg++) {
                const int cl = (tx << 2) + (cg << 6);
                float4 b4 = *(const float4*)&brow[cl];
                int4   m4 = *(const int4*)&mrow[cl];
                float4 p;
                p.x = m4.x ? __expf(fmaf(s[m][cg*4+0], scale, b4.x)) : 0.0f;
                p.y = m4.y ? __expf(fmaf(s[m][cg*4+1], scale, b4.y)) : 0.0f;
                p.z = m4.z ? __expf(fmaf(s[m][cg*4+2], scale, b4.z)) : 0.0f;
                p.w = m4.w ? __expf(fmaf(s[m][cg*4+3], scale, b4.w)) : 0.0f;
                rsum[m] += (p.x + p.y) + (p.z + p.w);
                *(float4*)&arow[cl] = p;
                *(float4*)&Ps[rl][cl] = p;
            }
        }
        __syncthreads();

        // P @ V accumulate (read P as float4 along k; per-phase broadcast)
        #pragma unroll 2
        for (int k4 = 0; k4 < 128; k4 += 4) {
            float4 v0 = *(const float4*)&Vs[k4+0][tx << 2];
            float4 v1 = *(const float4*)&Vs[k4+1][tx << 2];
            float4 v2 = *(const float4*)&Vs[k4+2][tx << 2];
            float4 v3 = *(const float4*)&Vs[k4+3][tx << 2];
            #pragma unroll
            for (int m = 0; m < 8; m++) {
                const int rl = (ty << 2) + ((m >> 2) << 6) + (m & 3);
                float4 pv = *(const float4*)&Ps[rl][k4];
                #pragma unroll
                for (int j = 0; j < 4; j++) {
                    float o = oacc[m][j];
                    o = fmaf(pv.x, (&v0.x)[j], o);
                    o = fmaf(pv.y, (&v1.x)[j], o);
                    o = fmaf(pv.z, (&v2.x)[j], o);
                    o = fmaf(pv.w, (&v3.x)[j], o);
                    oacc[m][j] = o;
                }
            }
        }
    }

    // rowsum reduce across tx (contiguous 16 lanes within warp)
    #pragma unroll
    for (int m = 0; m < 8; m++) {
        float v = rsum[m];
        v += __shfl_xor_sync(0xffffffffu, v, 1);
        v += __shfl_xor_sync(0xffffffffu, v, 2);
        v += __shfl_xor_sync(0xffffffffu, v, 4);
        v += __shfl_xor_sync(0xffffffffu, v, 8);
        rsum[m] = v;
    }

    #pragma unroll
    for (int m = 0; m < 8; m++) {
        const int rl = (ty << 2) + ((m >> 2) << 6) + (m & 3);
        const float inv = 1.0f / rsum[m];
        if (tx == 0)
            g_rowsum[(size_t)bh * SEQ + q0 + rl] = rsum[m];
        float4 o = make_float4(oacc[m][0] * inv, oacc[m][1] * inv,
                               oacc[m][2] * inv, oacc[m][3] * inv);
        *(float4*)&outp[((size_t)bh * SEQ + q0 + rl) * HD + (tx << 2)] = o;
    }
}

// ---------------------------------------------------------------------------
// Kernel 3: normalize attention weights by rowsum. One block per row.
// ---------------------------------------------------------------------------
__global__ __launch_bounds__(512) void norm_kernel(float* __restrict__ attn)
{
    const size_t row = blockIdx.x;
    const float inv = 1.0f / g_rowsum[row];
    float4* p = (float4*)(attn + row * SEQ);
    float4 v = p[threadIdx.x];
    v.x *= inv; v.y *= inv; v.z *= inv; v.w *= inv;
    p[threadIdx.x] = v;
}

// ---------------------------------------------------------------------------
extern "C" void kernel_launch(void* const* d_in, const int* in_sizes, int n_in,
                              void* d_out, int out_size)
{
    const float* x    = (const float*)d_in[0];
    const float* bias = (const float*)d_in[1];
    const int*   mask = (const int*)d_in[2];
    const float* wq   = (const float*)d_in[3];
    const float* bq   = (const float*)d_in[4];
    const float* wk   = (const float*)d_in[5];
    const float* bk   = (const float*)d_in[6];
    const float* wv   = (const float*)d_in[7];
    const float* bv   = (const float*)d_in[8];

    float* outp = (float*)d_out;                       // [2,16,2048,64]
    float* attn = outp + (size_t)BH * SEQ * HD;        // [2,16,2048,2048]

    cudaFuncSetAttribute(attn_kernel,
                         cudaFuncAttributeMaxDynamicSharedMemorySize,
                         ATTN_SMEM_BYTES);

    // 1) QKV projections (128x128 tiles)
    qkv_gemm_kernel<<<dim3(DM / 128, (BSZ * SEQ) / 128, 3), 256>>>(
        x, wq, bq, wk, bk, wv, bv);

    // 2) fused attention
    attn_kernel<<<dim3(SEQ / 128, BH), 256, ATTN_SMEM_BYTES>>>(
        bias, mask, outp, attn);

    // 3) normalize attention weights
    norm_kernel<<<dim3(BH * SEQ), 512>>>(attn);
}

// round 3
// speedup vs baseline: 1.0613x; 1.0601x over previous
#include <cuda_runtime.h>

#define BSZ 2
#define NH 16
#define SEQ 2048
#define DM 1024
#define HD 64
#define BH (BSZ*NH)

// Scratch (device globals — no allocations allowed)
__device__ float g_q[BH * SEQ * HD];
__device__ float g_k[BH * SEQ * HD];
__device__ float g_v[BH * SEQ * HD];
__device__ float g_rowsum[BH * SEQ];

// ---- packed f32x2 helpers (Blackwell paired-fp32 datapath) ------------------
typedef unsigned long long u64;

__device__ __forceinline__ u64 pack2(float x, float y) {
    u64 r; asm("mov.b64 %0, {%1, %2};" : "=l"(r) : "f"(x), "f"(y)); return r;
}
__device__ __forceinline__ u64 dup2(float x) {
    u64 r; asm("mov.b64 %0, {%1, %1};" : "=l"(r) : "f"(x)); return r;
}
__device__ __forceinline__ void unpack2(u64 v, float& x, float& y) {
    asm("mov.b64 {%0, %1}, %2;" : "=f"(x), "=f"(y) : "l"(v));
}
__device__ __forceinline__ void ffma2(u64& d, u64 a, u64 b) {
    asm("fma.rn.f32x2 %0, %1, %2, %0;" : "+l"(d) : "l"(a), "l"(b));
}

// ---------------------------------------------------------------------------
// Kernel 1: QKV projection. C[r][c] = sum_k x[r][k] * W[c][k] + b[c]
// 128x128 tile, K-slab 8, 256 threads, 8x8 micro-tile via f32x2 packed FMA,
// double-buffered smem, XOR-by-(k&4) swizzle.
// ---------------------------------------------------------------------------
__global__ __launch_bounds__(256, 2) void qkv_gemm_kernel(
    const float* __restrict__ x,
    const float* __restrict__ wq, const float* __restrict__ bq,
    const float* __restrict__ wk, const float* __restrict__ bk,
    const float* __restrict__ wv, const float* __restrict__ bv)
{
    __shared__ float As[2][8][128];
    __shared__ float Bs[2][8][128];

    const int z = blockIdx.z;
    const float* W    = (z == 0) ? wq : (z == 1) ? wk : wv;
    const float* bvec = (z == 0) ? bq : (z == 1) ? bk : bv;
    float* outp       = (z == 0) ? g_q : (z == 1) ? g_k : g_v;

    const int tid = threadIdx.x;
    const int tx = tid & 15, ty = tid >> 4;
    const int row0 = blockIdx.y << 7;
    const int col0 = blockIdx.x << 7;

    const int lr = tid >> 1;          // 0..127
    const int lk = (tid & 1) << 2;    // 0 or 4
    const int lc = lr ^ lk;           // swizzled store column

    const float* xg = x + (size_t)(row0 + lr) * DM + lk;
    const float* wg = W + (size_t)(col0 + lr) * DM + lk;

    u64 acc2[8][4];
    #pragma unroll
    for (int i = 0; i < 8; i++)
        #pragma unroll
        for (int j = 0; j < 4; j++) acc2[i][j] = 0ULL;

    float4 a = *(const float4*)xg;
    float4 b = *(const float4*)wg;
    #pragma unroll
    for (int j = 0; j < 4; j++) {
        As[0][lk + j][lc] = (&a.x)[j];
        Bs[0][lk + j][lc] = (&b.x)[j];
    }

    const int NIT = DM / 8;
    for (int it = 0; it < NIT; it++) {
        __syncthreads();
        const int buf = it & 1;
        if (it + 1 < NIT) {
            a = *(const float4*)(xg + (size_t)(it + 1) * 8);
            b = *(const float4*)(wg + (size_t)(it + 1) * 8);
        }
        #pragma unroll
        for (int k = 0; k < 8; k++) {
            const int s4 = k & 4;
            float4 a0 = *(const float4*)&As[buf][k][(ty << 2) ^ s4];
            float4 a1 = *(const float4*)&As[buf][k][((ty << 2) + 64) ^ s4];
            float4 b0 = *(const float4*)&Bs[buf][k][(tx << 2) ^ s4];
            float4 b1 = *(const float4*)&Bs[buf][k][((tx << 2) + 64) ^ s4];
            u64 kb2[4] = { pack2(b0.x, b0.y), pack2(b0.z, b0.w),
                           pack2(b1.x, b1.y), pack2(b1.z, b1.w) };
            float qa[8] = {a0.x, a0.y, a0.z, a0.w, a1.x, a1.y, a1.z, a1.w};
            #pragma unroll
            for (int i = 0; i < 8; i++) {
                u64 qq = dup2(qa[i]);
                #pragma unroll
                for (int j = 0; j < 4; j++)
                    ffma2(acc2[i][j], qq, kb2[j]);
            }
        }
        if (it + 1 < NIT) {
            #pragma unroll
            for (int j = 0; j < 4; j++) {
                As[buf ^ 1][lk + j][lc] = (&a.x)[j];
                Bs[buf ^ 1][lk + j][lc] = (&b.x)[j];
            }
        }
    }

    #pragma unroll
    for (int m = 0; m < 8; m++) {
        const int rl = (ty << 2) + ((m >> 2) << 6) + (m & 3);
        const int r = row0 + rl;
        const int bb = r >> 11;          // / SEQ
        const int ss = r & (SEQ - 1);
        #pragma unroll
        for (int cg = 0; cg < 2; cg++) {
            const int c = col0 + (tx << 2) + (cg << 6);
            const int h = c >> 6;
            const int d = c & 63;
            float e0, e1, e2, e3;
            unpack2(acc2[m][cg * 2 + 0], e0, e1);
            unpack2(acc2[m][cg * 2 + 1], e2, e3);
            float4 o;
            o.x = e0 + bvec[c + 0];
            o.y = e1 + bvec[c + 1];
            o.z = e2 + bvec[c + 2];
            o.w = e3 + bvec[c + 3];
            *(float4*)&outp[(((size_t)bb * NH + h) * SEQ + ss) * HD + d] = o;
        }
    }
}

// ---------------------------------------------------------------------------
// Kernel 2: fused attention with f32x2 packed FMA in both GEMM loops.
// ---------------------------------------------------------------------------
#define ATTN_SMEM_BYTES ((64*128 + 64*128 + 128*64 + 128*128) * 4)

__global__ __launch_bounds__(256, 1) void attn_kernel(
    const float* __restrict__ bias,
    const int*   __restrict__ mask,
    float* __restrict__ outp,
    float* __restrict__ attn)
{
    extern __shared__ float sm[];
    float (*Qs)[128] = (float(*)[128])(sm);            // [64 d][128 q] swizzled
    float (*Ks)[128] = (float(*)[128])(sm + 8192);     // [64 d][128 k] swizzled
    float (*Vs)[64]  = (float(*)[64]) (sm + 16384);    // [128 k][64 d]
    float (*Ps)[128] = (float(*)[128])(sm + 24576);    // [128 q][128 k]

    const int tid = threadIdx.x;
    const int tx = tid & 15, ty = tid >> 4;
    const int bh = blockIdx.y;
    const int h  = bh & (NH - 1);
    const int q0 = blockIdx.x << 7;
    const float scale = 0.125f;  // 1/sqrt(64)

    // Load Q tile (128 x 64), transposed + swizzled
    const float* Qg = g_q + ((size_t)bh * SEQ + q0) * HD;
    #pragma unroll
    for (int it = 0; it < 8; it++) {
        int idx = tid + it * 256;       // 0..2047
        int r  = idx >> 4;              // 0..127
        int d4 = (idx & 15) << 2;       // 0..60
        float4 v = *(const float4*)&Qg[r * HD + d4];
        int cs = r ^ d4;
        Qs[d4+0][cs] = v.x; Qs[d4+1][cs] = v.y;
        Qs[d4+2][cs] = v.z; Qs[d4+3][cs] = v.w;
    }

    u64 oacc2[8][2];
    #pragma unroll
    for (int m = 0; m < 8; m++) { oacc2[m][0] = 0ULL; oacc2[m][1] = 0ULL; }
    float rsum[8] = {};

    for (int kt = 0; kt < SEQ / 128; kt++) {
        const int k0 = kt << 7;
        const float* Kg = g_k + ((size_t)bh * SEQ + k0) * HD;
        const float* Vg = g_v + ((size_t)bh * SEQ + k0) * HD;

        __syncthreads();   // previous PV done before overwriting Ks/Vs
        #pragma unroll
        for (int it = 0; it < 8; it++) {
            int idx = tid + it * 256;
            int r  = idx >> 4;
            int d4 = (idx & 15) << 2;
            float4 kv = *(const float4*)&Kg[r * HD + d4];
            int cs = r ^ d4;
            Ks[d4+0][cs] = kv.x; Ks[d4+1][cs] = kv.y;
            Ks[d4+2][cs] = kv.z; Ks[d4+3][cs] = kv.w;
            float4 vv = *(const float4*)&Vg[r * HD + d4];
            *(float4*)&Vs[r][d4] = vv;
        }
        __syncthreads();

        // S = Q K^T  (8x8 micro-tile, packed f32x2)
        u64 s2[8][4];
        #pragma unroll
        for (int i = 0; i < 8; i++)
            #pragma unroll
            for (int j = 0; j < 4; j++) s2[i][j] = 0ULL;

        #pragma unroll 8
        for (int d = 0; d < 64; d++) {
            const int s4 = d & 60;
            float4 q0v = *(const float4*)&Qs[d][(ty << 2) ^ s4];
            float4 q1v = *(const float4*)&Qs[d][((ty << 2) + 64) ^ s4];
            float4 k0v = *(const float4*)&Ks[d][(tx << 2) ^ s4];
            float4 k1v = *(const float4*)&Ks[d][((tx << 2) + 64) ^ s4];
            u64 kb2[4] = { pack2(k0v.x, k0v.y), pack2(k0v.z, k0v.w),
                           pack2(k1v.x, k1v.y), pack2(k1v.z, k1v.w) };
            float qa[8] = {q0v.x, q0v.y, q0v.z, q0v.w, q1v.x, q1v.y, q1v.z, q1v.w};
            #pragma unroll
            for (int i = 0; i < 8; i++) {
                u64 qq = dup2(qa[i]);
                #pragma unroll
                for (int j = 0; j < 4; j++)
                    ffma2(s2[i][j], qq, kb2[j]);
            }
        }

        // epilogue: bias + mask + exp; store unnormalized attn; stage P
        #pragma unroll
        for (int m = 0; m < 8; m++) {
            const int rl = (ty << 2) + ((m >> 2) << 6) + (m & 3);
            const int qg = q0 + rl;
            const float* brow = bias + ((size_t)h * SEQ + qg) * SEQ + k0;
            const int*   mrow = mask + (size_t)qg * SEQ + k0;
            float*       arow = attn + ((size_t)bh * SEQ + qg) * SEQ + k0;
            #pragma unroll
            for (int cg = 0; cg < 2; cg++) {
                const int cl = (tx << 2) + (cg << 6);
                float4 b4 = *(const float4*)&brow[cl];
                int4   m4 = *(const int4*)&mrow[cl];
                float s0, s1, sA, sB;
                unpack2(s2[m][cg * 2 + 0], s0, s1);
                unpack2(s2[m][cg * 2 + 1], sA, sB);
                float4 p;
                p.x = m4.x ? __expf(fmaf(s0, scale, b4.x)) : 0.0f;
                p.y = m4.y ? __expf(fmaf(s1, scale, b4.y)) : 0.0f;
                p.z = m4.z ? __expf(fmaf(sA, scale, b4.z)) : 0.0f;
                p.w = m4.w ? __expf(fmaf(sB, scale, b4.w)) : 0.0f;
                rsum[m] += (p.x + p.y) + (p.z + p.w);
                *(float4*)&arow[cl] = p;
                *(float4*)&Ps[rl][cl] = p;
            }
        }
        __syncthreads();

        // P @ V accumulate (packed f32x2; V pairs along d, P broadcast)
        #pragma unroll 2
        for (int k4 = 0; k4 < 128; k4 += 4) {
            float4 v0 = *(const float4*)&Vs[k4+0][tx << 2];
            float4 v1 = *(const float4*)&Vs[k4+1][tx << 2];
            float4 v2 = *(const float4*)&Vs[k4+2][tx << 2];
            float4 v3 = *(const float4*)&Vs[k4+3][tx << 2];
            u64 vp[4][2] = {
                { pack2(v0.x, v0.y), pack2(v0.z, v0.w) },
                { pack2(v1.x, v1.y), pack2(v1.z, v1.w) },
                { pack2(v2.x, v2.y), pack2(v2.z, v2.w) },
                { pack2(v3.x, v3.y), pack2(v3.z, v3.w) } };
            #pragma unroll
            for (int m = 0; m < 8; m++) {
                const int rl = (ty << 2) + ((m >> 2) << 6) + (m & 3);
                float4 pv = *(const float4*)&Ps[rl][k4];
                u64 p0 = dup2(pv.x), p1 = dup2(pv.y);
                u64 p2 = dup2(pv.z), p3 = dup2(pv.w);
                #pragma unroll
                for (int jp = 0; jp < 2; jp++) {
                    ffma2(oacc2[m][jp], p0, vp[0][jp]);
                    ffma2(oacc2[m][jp], p1, vp[1][jp]);
                    ffma2(oacc2[m][jp], p2, vp[2][jp]);
                    ffma2(oacc2[m][jp], p3, vp[3][jp]);
                }
            }
        }
    }

    // rowsum reduce across tx (contiguous 16 lanes within warp)
    #pragma unroll
    for (int m = 0; m < 8; m++) {
        float v = rsum[m];
        v += __shfl_xor_sync(0xffffffffu, v, 1);
        v += __shfl_xor_sync(0xffffffffu, v, 2);
        v += __shfl_xor_sync(0xffffffffu, v, 4);
        v += __shfl_xor_sync(0xffffffffu, v, 8);
        rsum[m] = v;
    }

    #pragma unroll
    for (int m = 0; m < 8; m++) {
        const int rl = (ty << 2) + ((m >> 2) << 6) + (m & 3);
        const float inv = 1.0f / rsum[m];
        if (tx == 0)
            g_rowsum[(size_t)bh * SEQ + q0 + rl] = rsum[m];
        float o0, o1, o2, o3;
        unpack2(oacc2[m][0], o0, o1);
        unpack2(oacc2[m][1], o2, o3);
        float4 o = make_float4(o0 * inv, o1 * inv, o2 * inv, o3 * inv);
        *(float4*)&outp[((size_t)bh * SEQ + q0 + rl) * HD + (tx << 2)] = o;
    }
}

// ---------------------------------------------------------------------------
// Kernel 3: normalize attention weights by rowsum. One block per row.
// ---------------------------------------------------------------------------
__global__ __launch_bounds__(512) void norm_kernel(float* __restrict__ attn)
{
    const size_t row = blockIdx.x;
    const float inv = 1.0f / g_rowsum[row];
    float4* p = (float4*)(attn + row * SEQ);
    float4 v = p[threadIdx.x];
    v.x *= inv; v.y *= inv; v.z *= inv; v.w *= inv;
    p[threadIdx.x] = v;
}

// ---------------------------------------------------------------------------
extern "C" void kernel_launch(void* const* d_in, const int* in_sizes, int n_in,
                              void* d_out, int out_size)
{
    const float* x    = (const float*)d_in[0];
    const float* bias = (const float*)d_in[1];
    const int*   mask = (const int*)d_in[2];
    const float* wq   = (const float*)d_in[3];
    const float* bq   = (const float*)d_in[4];
    const float* wk   = (const float*)d_in[5];
    const float* bk   = (const float*)d_in[6];
    const float* wv   = (const float*)d_in[7];
    const float* bv   = (const float*)d_in[8];

    float* outp = (float*)d_out;                       // [2,16,2048,64]
    float* attn = outp + (size_t)BH * SEQ * HD;        // [2,16,2048,2048]

    cudaFuncSetAttribute(attn_kernel,
                         cudaFuncAttributeMaxDynamicSharedMemorySize,
                         ATTN_SMEM_BYTES);

    // 1) QKV projections (128x128 tiles)
    qkv_gemm_kernel<<<dim3(DM / 128, (BSZ * SEQ) / 128, 3), 256>>>(
        x, wq, bq, wk, bk, wv, bv);

    // 2) fused attention
    attn_kernel<<<dim3(SEQ / 128, BH), 256, ATTN_SMEM_BYTES>>>(
        bias, mask, outp, attn);

    // 3) normalize attention weights
    norm_kernel<<<dim3(BH * SEQ), 512>>>(attn);
}

// round 5
// speedup vs baseline: 1.2542x; 1.1818x over previous
#include <cuda_runtime.h>
#include <cuda_bf16.h>
#include <cstdint>

#define BSZ 2
#define NH 16
#define SEQ 2048
#define DM 1024
#define HD 64
#define BH (BSZ*NH)

// Scratch (device globals — no allocations allowed)
__device__ __nv_bfloat16 g_q_hi[BH * SEQ * HD];
__device__ __nv_bfloat16 g_q_lo[BH * SEQ * HD];
__device__ __nv_bfloat16 g_k_hi[BH * SEQ * HD];
__device__ __nv_bfloat16 g_k_lo[BH * SEQ * HD];
__device__ __nv_bfloat16 g_v_hi[BH * SEQ * HD];
__device__ __nv_bfloat16 g_v_lo[BH * SEQ * HD];
__device__ float g_rowsum[BH * SEQ];

// ---- packed f32x2 helpers ---------------------------------------------------
typedef unsigned long long u64;
__device__ __forceinline__ u64 pack2(float x, float y) {
    u64 r; asm("mov.b64 %0, {%1, %2};" : "=l"(r) : "f"(x), "f"(y)); return r;
}
__device__ __forceinline__ u64 dup2(float x) {
    u64 r; asm("mov.b64 %0, {%1, %1};" : "=l"(r) : "f"(x)); return r;
}
__device__ __forceinline__ void unpack2(u64 v, float& x, float& y) {
    asm("mov.b64 {%0, %1}, %2;" : "=f"(x), "=f"(y) : "l"(v));
}
__device__ __forceinline__ void ffma2(u64& d, u64 a, u64 b) {
    asm("fma.rn.f32x2 %0, %1, %2, %0;" : "+l"(d) : "l"(a), "l"(b));
}

// ---- bf16 split helper: hi = bf16(a,b) packed (lo-half = a); lo = residual --
__device__ __forceinline__ void split2(float a, float b, uint32_t& hi, uint32_t& lo) {
    __nv_bfloat162 h = __floats2bfloat162_rn(a, b);
    float2 hf = __bfloat1622float2(h);
    __nv_bfloat162 l = __floats2bfloat162_rn(a - hf.x, b - hf.y);
    hi = *reinterpret_cast<uint32_t*>(&h);
    lo = *reinterpret_cast<uint32_t*>(&l);
}

// ---- smem addr / ldmatrix / mma primitives (sm_80-class, compile for sm_103) -
__device__ __forceinline__ uint32_t smem_u32(const void* p) {
    uint32_t a;
    asm("{ .reg .u64 t; cvta.to.shared.u64 t, %1; cvt.u32.u64 %0, t; }"
        : "=r"(a) : "l"(p));
    return a;
}
// tile rows are 128B (64 bf16); XOR swizzle 16B-chunk by (row&7)
__device__ __forceinline__ uint32_t swz_addr(uint32_t base, int row, int chunk) {
    uint32_t off = (uint32_t)(row * 128 + chunk * 16);
    return base + (off ^ ((off >> 3) & 0x70));
}
__device__ __forceinline__ void ldsm_x4(uint32_t* r, uint32_t a) {
    asm volatile("ldmatrix.sync.aligned.m8n8.x4.shared.b16 {%0,%1,%2,%3}, [%4];"
        : "=r"(r[0]), "=r"(r[1]), "=r"(r[2]), "=r"(r[3]) : "r"(a));
}
__device__ __forceinline__ void ldsm_x4t(uint32_t* r, uint32_t a) {
    asm volatile("ldmatrix.sync.aligned.m8n8.x4.trans.shared.b16 {%0,%1,%2,%3}, [%4];"
        : "=r"(r[0]), "=r"(r[1]), "=r"(r[2]), "=r"(r[3]) : "r"(a));
}
__device__ __forceinline__ void mma_bf16(float* d, const uint32_t* a,
                                         uint32_t b0, uint32_t b1) {
    asm volatile("mma.sync.aligned.m16n8k16.row.col.f32.bf16.bf16.f32 "
        "{%0,%1,%2,%3}, {%4,%5,%6,%7}, {%8,%9}, {%0,%1,%2,%3};"
        : "+f"(d[0]), "+f"(d[1]), "+f"(d[2]), "+f"(d[3])
        : "r"(a[0]), "r"(a[1]), "r"(a[2]), "r"(a[3]), "r"(b0), "r"(b1));
}

// ---------------------------------------------------------------------------
// Kernel 1: QKV projection (f32x2 SIMT) -> split-bf16 outputs, head-split.
// ---------------------------------------------------------------------------
__global__ __launch_bounds__(256, 2) void qkv_gemm_kernel(
    const float* __restrict__ x,
    const float* __restrict__ wq, const float* __restrict__ bq,
    const float* __restrict__ wk, const float* __restrict__ bk,
    const float* __restrict__ wv, const float* __restrict__ bv)
{
    __shared__ float As[2][8][128];
    __shared__ float Bs[2][8][128];

    const int z = blockIdx.z;
    const float* W    = (z == 0) ? wq : (z == 1) ? wk : wv;
    const float* bvec = (z == 0) ? bq : (z == 1) ? bk : bv;
    __nv_bfloat16* ohi = (z == 0) ? g_q_hi : (z == 1) ? g_k_hi : g_v_hi;
    __nv_bfloat16* olo = (z == 0) ? g_q_lo : (z == 1) ? g_k_lo : g_v_lo;

    const int tid = threadIdx.x;
    const int tx = tid & 15, ty = tid >> 4;
    const int row0 = blockIdx.y << 7;
    const int col0 = blockIdx.x << 7;

    const int lr = tid >> 1;
    const int lk = (tid & 1) << 2;
    const int lc = lr ^ lk;

    const float* xg = x + (size_t)(row0 + lr) * DM + lk;
    const float* wg = W + (size_t)(col0 + lr) * DM + lk;

    u64 acc2[8][4];
    #pragma unroll
    for (int i = 0; i < 8; i++)
        #pragma unroll
        for (int j = 0; j < 4; j++) acc2[i][j] = 0ULL;

    float4 a = *(const float4*)xg;
    float4 b = *(const float4*)wg;
    #pragma unroll
    for (int j = 0; j < 4; j++) {
        As[0][lk + j][lc] = (&a.x)[j];
        Bs[0][lk + j][lc] = (&b.x)[j];
    }

    const int NIT = DM / 8;
    for (int it = 0; it < NIT; it++) {
        __syncthreads();
        const int buf = it & 1;
        if (it + 1 < NIT) {
            a = *(const float4*)(xg + (size_t)(it + 1) * 8);
            b = *(const float4*)(wg + (size_t)(it + 1) * 8);
        }
        #pragma unroll
        for (int k = 0; k < 8; k++) {
            const int s4 = k & 4;
            float4 a0 = *(const float4*)&As[buf][k][(ty << 2) ^ s4];
            float4 a1 = *(const float4*)&As[buf][k][((ty << 2) + 64) ^ s4];
            float4 b0 = *(const float4*)&Bs[buf][k][(tx << 2) ^ s4];
            float4 b1 = *(const float4*)&Bs[buf][k][((tx << 2) + 64) ^ s4];
            u64 kb2[4] = { pack2(b0.x, b0.y), pack2(b0.z, b0.w),
                           pack2(b1.x, b1.y), pack2(b1.z, b1.w) };
            float qa[8] = {a0.x, a0.y, a0.z, a0.w, a1.x, a1.y, a1.z, a1.w};
            #pragma unroll
            for (int i = 0; i < 8; i++) {
                u64 qq = dup2(qa[i]);
                #pragma unroll
                for (int j = 0; j < 4; j++)
                    ffma2(acc2[i][j], qq, kb2[j]);
            }
        }
        if (it + 1 < NIT) {
            #pragma unroll
            for (int j = 0; j < 4; j++) {
                As[buf ^ 1][lk + j][lc] = (&a.x)[j];
                Bs[buf ^ 1][lk + j][lc] = (&b.x)[j];
            }
        }
    }

    #pragma unroll
    for (int m = 0; m < 8; m++) {
        const int rl = (ty << 2) + ((m >> 2) << 6) + (m & 3);
        const int r = row0 + rl;
        const int bb = r >> 11;
        const int ss = r & (SEQ - 1);
        #pragma unroll
        for (int cg = 0; cg < 2; cg++) {
            const int c = col0 + (tx << 2) + (cg << 6);
            const int h = c >> 6;
            const int d = c & 63;
            float e0, e1, e2, e3;
            unpack2(acc2[m][cg * 2 + 0], e0, e1);
            unpack2(acc2[m][cg * 2 + 1], e2, e3);
            e0 += bvec[c + 0]; e1 += bvec[c + 1];
            e2 += bvec[c + 2]; e3 += bvec[c + 3];
            uint32_t h01, l01, h23, l23;
            split2(e0, e1, h01, l01);
            split2(e2, e3, h23, l23);
            const size_t e = (((size_t)bb * NH + h) * SEQ + ss) * HD + d;
            *(uint2*)&ohi[e] = make_uint2(h01, h23);
            *(uint2*)&olo[e] = make_uint2(l01, l23);
        }
    }
}

// ---------------------------------------------------------------------------
// Kernel 2: mma.sync (HMMA bf16) attention, bf16x3 split precision.
// CTA = 128 q-rows x one (b,h); 8 warps, warp w owns q rows [16w,16w+16).
// Per 128-k tile: S = QK^T (3 bf16 mma chains, f32 accum) -> register epilogue
// (bias+mask+exp -> attn gmem, pack P hi/lo A-frags) -> PV accumulate.
// ---------------------------------------------------------------------------
#define SM_QH 0
#define SM_QL 16384
#define SM_KH 32768
#define SM_KL 49152
#define SM_VH 65536
#define SM_VL 81920
#define ATTN_SMEM_BYTES 98304

__global__ __launch_bounds__(256, 1) void attn_mma_kernel(
    const float* __restrict__ bias,
    const int*   __restrict__ mask,
    float* __restrict__ outp,
    float* __restrict__ attn)
{
    extern __shared__ char smem[];
    const uint32_t sb = smem_u32(smem);

    const int tid = threadIdx.x;
    const int wid = tid >> 5, lane = tid & 31;
    const int bh = blockIdx.y;
    const int h  = bh & (NH - 1);
    const int q0 = blockIdx.x << 7;
    const float scale = 0.125f;
    const size_t bhbase = (size_t)bh * SEQ;

    // generic 128x64-bf16 tile loader into swizzled smem
    auto load_tile = [&](const __nv_bfloat16* src, int smoff) {
        const uint4* s4 = (const uint4*)src;
        #pragma unroll
        for (int it = 0; it < 4; it++) {
            int idx = tid + it * 256;           // 0..1023
            int r = idx >> 3, c = idx & 7;
            uint32_t off = (uint32_t)(r * 128 + c * 16);
            off ^= (off >> 3) & 0x70;
            *(uint4*)(smem + smoff + off) = s4[idx];
        }
    };

    // ---- load Q tile and hoist Q fragments (row-major A, no trans) ----
    load_tile(g_q_hi + (bhbase + q0) * HD, SM_QH);
    load_tile(g_q_lo + (bhbase + q0) * HD, SM_QL);
    __syncthreads();

    uint32_t qh[4][4], ql[4][4];
    {
        const int rA = (wid << 4) + (lane & 7) + ((lane >> 3) & 1) * 8;
        #pragma unroll
        for (int ks = 0; ks < 4; ks++) {
            const int ch = ks * 2 + (lane >> 4);
            ldsm_x4(qh[ks], swz_addr(sb + SM_QH, rA, ch));
            ldsm_x4(ql[ks], swz_addr(sb + SM_QL, rA, ch));
        }
    }

    float o[8][4];
    #pragma unroll
    for (int g = 0; g < 8; g++)
        #pragma unroll
        for (int j = 0; j < 4; j++) o[g][j] = 0.0f;
    float rsum1 = 0.0f, rsum2 = 0.0f;

    const int r1 = (wid << 4) + (lane >> 2);   // q row (first of pair)
    const int qg1 = q0 + r1, qg2 = qg1 + 8;
    const float* brow1 = bias + ((size_t)h * SEQ + qg1) * SEQ;
    const float* brow2 = bias + ((size_t)h * SEQ + qg2) * SEQ;
    const int*   mrow1 = mask + (size_t)qg1 * SEQ;
    const int*   mrow2 = mask + (size_t)qg2 * SEQ;
    float*       arow1 = attn + (bhbase + qg1) * SEQ;
    float*       arow2 = attn + (bhbase + qg2) * SEQ;

    for (int kt = 0; kt < SEQ / 128; kt++) {
        const int k0 = kt << 7;
        __syncthreads();   // previous tile's ldmatrix reads complete
        load_tile(g_k_hi + (bhbase + k0) * HD, SM_KH);
        load_tile(g_k_lo + (bhbase + k0) * HD, SM_KL);
        load_tile(g_v_hi + (bhbase + k0) * HD, SM_VH);
        load_tile(g_v_lo + (bhbase + k0) * HD, SM_VL);
        __syncthreads();

        // ---- S = Q K^T over 128 cols (16 n8-groups), bf16x3 ----
        float s[16][4];
        #pragma unroll
        for (int g = 0; g < 16; g++)
            #pragma unroll
            for (int j = 0; j < 4; j++) s[g][j] = 0.0f;

        #pragma unroll
        for (int nf = 0; nf < 8; nf++) {
            const int rB = nf * 16 + (lane & 7) + (lane >> 4) * 8;
            #pragma unroll
            for (int ks = 0; ks < 4; ks++) {
                const int ch = ks * 2 + ((lane >> 3) & 1);
                uint32_t kh4[4], kl4[4];
                ldsm_x4(kh4, swz_addr(sb + SM_KH, rB, ch));
                ldsm_x4(kl4, swz_addr(sb + SM_KL, rB, ch));
                mma_bf16(s[2*nf],   qh[ks], kh4[0], kh4[1]);
                mma_bf16(s[2*nf+1], qh[ks], kh4[2], kh4[3]);
                mma_bf16(s[2*nf],   qh[ks], kl4[0], kl4[1]);
                mma_bf16(s[2*nf+1], qh[ks], kl4[2], kl4[3]);
                mma_bf16(s[2*nf],   ql[ks], kh4[0], kh4[1]);
                mma_bf16(s[2*nf+1], ql[ks], kh4[2], kh4[3]);
            }
        }

        // ---- register epilogue: bias + mask + exp; attn store; pack P ----
        uint32_t ph[8][4], pl[8][4];
        #pragma unroll
        for (int g = 0; g < 16; g++) {
            const int c = k0 + g * 8 + (lane & 3) * 2;
            float2 bA = *(const float2*)(brow1 + c);
            float2 bB = *(const float2*)(brow2 + c);
            int2   mA = *(const int2*)(mrow1 + c);
            int2   mB = *(const int2*)(mrow2 + c);
            float p0 = mA.x ? __expf(fmaf(s[g][0], scale, bA.x)) : 0.0f;
            float p1 = mA.y ? __expf(fmaf(s[g][1], scale, bA.y)) : 0.0f;
            float p2 = mB.x ? __expf(fmaf(s[g][2], scale, bB.x)) : 0.0f;
            float p3 = mB.y ? __expf(fmaf(s[g][3], scale, bB.y)) : 0.0f;
            rsum1 += p0 + p1;
            rsum2 += p2 + p3;
            *(float2*)(arow1 + c) = make_float2(p0, p1);
            *(float2*)(arow2 + c) = make_float2(p2, p3);
            const int ks = g >> 1, ix = (g & 1) * 2;
            split2(p0, p1, ph[ks][ix + 0], pl[ks][ix + 0]);  // a0 / a2
            split2(p2, p3, ph[ks][ix + 1], pl[ks][ix + 1]);  // a1 / a3
        }

        // ---- O += P V (bf16x3): B = V via ldmatrix.trans ----
        #pragma unroll
        for (int ks = 0; ks < 8; ks++) {
            const int rV = ks * 16 + (lane & 7) + ((lane >> 3) & 1) * 8;
            #pragma unroll
            for (int dg = 0; dg < 4; dg++) {
                const int ch = 2 * dg + (lane >> 4);
                uint32_t vh4[4], vl4[4];
                ldsm_x4t(vh4, swz_addr(sb + SM_VH, rV, ch));
                ldsm_x4t(vl4, swz_addr(sb + SM_VL, rV, ch));
                mma_bf16(o[2*dg],   ph[ks], vh4[0], vh4[1]);
                mma_bf16(o[2*dg+1], ph[ks], vh4[2], vh4[3]);
                mma_bf16(o[2*dg],   ph[ks], vl4[0], vl4[1]);
                mma_bf16(o[2*dg+1], ph[ks], vl4[2], vl4[3]);
                mma_bf16(o[2*dg],   pl[ks], vh4[0], vh4[1]);
                mma_bf16(o[2*dg+1], pl[ks], vh4[2], vh4[3]);
            }
        }
    }

    // ---- rowsum quad-reduce (lanes sharing a row differ in lane&3) ----
    rsum1 += __shfl_xor_sync(0xffffffffu, rsum1, 1);
    rsum1 += __shfl_xor_sync(0xffffffffu, rsum1, 2);
    rsum2 += __shfl_xor_sync(0xffffffffu, rsum2, 1);
    rsum2 += __shfl_xor_sync(0xffffffffu, rsum2, 2);
    if ((lane & 3) == 0) {
        g_rowsum[bhbase + qg1] = rsum1;
        g_rowsum[bhbase + qg2] = rsum2;
    }
    const float inv1 = 1.0f / rsum1;
    const float inv2 = 1.0f / rsum2;

    float* or1 = outp + (bhbase + qg1) * HD;
    float* or2 = outp + (bhbase + qg2) * HD;
    #pragma unroll
    for (int g = 0; g < 8; g++) {
        const int c = g * 8 + (lane & 3) * 2;
        *(float2*)(or1 + c) = make_float2(o[g][0] * inv1, o[g][1] * inv1);
        *(float2*)(or2 + c) = make_float2(o[g][2] * inv2, o[g][3] * inv2);
    }
}

// ---------------------------------------------------------------------------
// Kernel 3: normalize attention weights by rowsum. One block per row.
// ---------------------------------------------------------------------------
__global__ __launch_bounds__(512) void norm_kernel(float* __restrict__ attn)
{
    const size_t row = blockIdx.x;
    const float inv = 1.0f / g_rowsum[row];
    float4* p = (float4*)(attn + row * SEQ);
    float4 v = p[threadIdx.x];
    v.x *= inv; v.y *= inv; v.z *= inv; v.w *= inv;
    p[threadIdx.x] = v;
}

// ---------------------------------------------------------------------------
extern "C" void kernel_launch(void* const* d_in, const int* in_sizes, int n_in,
                              void* d_out, int out_size)
{
    const float* x    = (const float*)d_in[0];
    const float* bias = (const float*)d_in[1];
    const int*   mask = (const int*)d_in[2];
    const float* wq   = (const float*)d_in[3];
    const float* bq   = (const float*)d_in[4];
    const float* wk   = (const float*)d_in[5];
    const float* bk   = (const float*)d_in[6];
    const float* wv   = (const float*)d_in[7];
    const float* bv   = (const float*)d_in[8];

    float* outp = (float*)d_out;                       // [2,16,2048,64]
    float* attn = outp + (size_t)BH * SEQ * HD;        // [2,16,2048,2048]

    cudaFuncSetAttribute(attn_mma_kernel,
                         cudaFuncAttributeMaxDynamicSharedMemorySize,
                         ATTN_SMEM_BYTES);

    // 1) QKV projections -> split-bf16 Q/K/V
    qkv_gemm_kernel<<<dim3(DM / 128, (BSZ * SEQ) / 128, 3), 256>>>(
        x, wq, bq, wk, bk, wv, bv);

    // 2) HMMA fused attention
    attn_mma_kernel<<<dim3(SEQ / 128, BH), 256, ATTN_SMEM_BYTES>>>(
        bias, mask, outp, attn);

    // 3) normalize attention weights
    norm_kernel<<<dim3(BH * SEQ), 512>>>(attn);
}

// round 6
// speedup vs baseline: 1.5999x; 1.2756x over previous
#include <cuda_runtime.h>
#include <cuda_bf16.h>
#include <cstdint>

#define BSZ 2
#define NH 16
#define SEQ 2048
#define DM 1024
#define HD 64
#define BH (BSZ*NH)

// Scratch (device globals — no allocations allowed)
__device__ __nv_bfloat16 g_xh[BSZ*SEQ*DM];
__device__ __nv_bfloat16 g_xl[BSZ*SEQ*DM];
__device__ __nv_bfloat16 g_wh[3*DM*DM];
__device__ __nv_bfloat16 g_wl[3*DM*DM];
__device__ __nv_bfloat16 g_q_hi[BH * SEQ * HD];
__device__ __nv_bfloat16 g_q_lo[BH * SEQ * HD];
__device__ __nv_bfloat16 g_k_hi[BH * SEQ * HD];
__device__ __nv_bfloat16 g_k_lo[BH * SEQ * HD];
__device__ __nv_bfloat16 g_v_hi[BH * SEQ * HD];
__device__ __nv_bfloat16 g_v_lo[BH * SEQ * HD];
__device__ float g_rowsum[BH * SEQ];

// ---- bf16 split: hi = bf16x2(a,b); lo = bf16x2 residual ---------------------
__device__ __forceinline__ void split2(float a, float b, uint32_t& hi, uint32_t& lo) {
    __nv_bfloat162 h = __floats2bfloat162_rn(a, b);
    float2 hf = __bfloat1622float2(h);
    __nv_bfloat162 l = __floats2bfloat162_rn(a - hf.x, b - hf.y);
    hi = *reinterpret_cast<uint32_t*>(&h);
    lo = *reinterpret_cast<uint32_t*>(&l);
}

// ---- smem / ldmatrix / mma / cp.async primitives ----------------------------
__device__ __forceinline__ uint32_t smem_u32(const void* p) {
    uint32_t a;
    asm("{ .reg .u64 t; cvta.to.shared.u64 t, %1; cvt.u32.u64 %0, t; }"
        : "=r"(a) : "l"(p));
    return a;
}
// tile rows are 128B (64 bf16); XOR swizzle 16B-chunk by (row&7)
__device__ __forceinline__ uint32_t swz_addr(uint32_t base, int row, int chunk) {
    uint32_t off = (uint32_t)(row * 128 + chunk * 16);
    return base + (off ^ ((off >> 3) & 0x70));
}
__device__ __forceinline__ void ldsm_x4(uint32_t* r, uint32_t a) {
    asm volatile("ldmatrix.sync.aligned.m8n8.x4.shared.b16 {%0,%1,%2,%3}, [%4];"
        : "=r"(r[0]), "=r"(r[1]), "=r"(r[2]), "=r"(r[3]) : "r"(a));
}
__device__ __forceinline__ void ldsm_x4t(uint32_t* r, uint32_t a) {
    asm volatile("ldmatrix.sync.aligned.m8n8.x4.trans.shared.b16 {%0,%1,%2,%3}, [%4];"
        : "=r"(r[0]), "=r"(r[1]), "=r"(r[2]), "=r"(r[3]) : "r"(a));
}
__device__ __forceinline__ void mma_bf16(float* d, const uint32_t* a,
                                         uint32_t b0, uint32_t b1) {
    asm volatile("mma.sync.aligned.m16n8k16.row.col.f32.bf16.bf16.f32 "
        "{%0,%1,%2,%3}, {%4,%5,%6,%7}, {%8,%9}, {%0,%1,%2,%3};"
        : "+f"(d[0]), "+f"(d[1]), "+f"(d[2]), "+f"(d[3])
        : "r"(a[0]), "r"(a[1]), "r"(a[2]), "r"(a[3]), "r"(b0), "r"(b1));
}
__device__ __forceinline__ void cp16(uint32_t dst, const void* src) {
    asm volatile("cp.async.cg.shared.global [%0], [%1], 16;"
                 :: "r"(dst), "l"(src) : "memory");
}
#define CP_COMMIT() asm volatile("cp.async.commit_group;" ::: "memory")
#define CP_WAIT1()  asm volatile("cp.async.wait_group 1;" ::: "memory")

// ---------------------------------------------------------------------------
// Kernel 0: split fp32 sources into hi/lo bf16 buffers (x, wq, wk, wv).
// ---------------------------------------------------------------------------
__global__ __launch_bounds__(256) void split_src_kernel(
    const float* __restrict__ x,
    const float* __restrict__ wq, const float* __restrict__ wk,
    const float* __restrict__ wv)
{
    const int z = blockIdx.y;
    const float* src;
    uint32_t *oh, *ol;
    size_t n2;
    if (z == 0) {
        src = x; oh = (uint32_t*)g_xh; ol = (uint32_t*)g_xl;
        n2 = (size_t)BSZ * SEQ * DM / 2;
    } else {
        src = (z == 1) ? wq : (z == 2) ? wk : wv;
        oh = (uint32_t*)(g_wh + (size_t)(z - 1) * DM * DM);
        ol = (uint32_t*)(g_wl + (size_t)(z - 1) * DM * DM);
        n2 = (size_t)DM * DM / 2;
    }
    for (size_t i = (size_t)blockIdx.x * 256 + threadIdx.x; i < n2;
         i += (size_t)gridDim.x * 256) {
        float2 v = ((const float2*)src)[i];
        uint32_t hi, lo;
        split2(v.x, v.y, hi, lo);
        oh[i] = hi; ol[i] = lo;
    }
}

// ---------------------------------------------------------------------------
// Kernel 1: QKV projection via HMMA bf16x3: C = x W^T + b -> split-bf16 out.
// 128x128 tile, K-slab 64, 8 warps (warp = 16 rows x 128 cols),
// cp.async double-buffered smem (XH/XL/WH/WL per stage).
// ---------------------------------------------------------------------------
#define QKV_SMEM_BYTES 131072

__global__ __launch_bounds__(256, 1) void qkv_hmma_kernel(
    const float* __restrict__ bq, const float* __restrict__ bk,
    const float* __restrict__ bv)
{
    extern __shared__ char smem[];
    const uint32_t sb = smem_u32(smem);
    const int tid = threadIdx.x, wid = tid >> 5, lane = tid & 31;
    const int z = blockIdx.z;
    const float* bvec = (z == 0) ? bq : (z == 1) ? bk : bv;
    __nv_bfloat16* ohi = (z == 0) ? g_q_hi : (z == 1) ? g_k_hi : g_v_hi;
    __nv_bfloat16* olo = (z == 0) ? g_q_lo : (z == 1) ? g_k_lo : g_v_lo;
    const __nv_bfloat16* WH = g_wh + (size_t)z * DM * DM;
    const __nv_bfloat16* WL = g_wl + (size_t)z * DM * DM;
    const int col0 = blockIdx.x << 7;
    const int row0 = blockIdx.y << 7;

    auto issue = [&](int slab, int buf) {
        const int k0 = slab << 6;
        const uint32_t base = sb + (uint32_t)buf * 65536;
        #pragma unroll
        for (int it = 0; it < 4; it++) {
            const int idx = tid + it * 256;     // 0..1023
            const int r = idx >> 3, c = idx & 7;
            uint32_t off = (uint32_t)(r * 128 + c * 16);
            off ^= (off >> 3) & 0x70;
            const size_t gx = (size_t)(row0 + r) * DM + k0 + c * 8;
            const size_t gw = (size_t)(col0 + r) * DM + k0 + c * 8;
            cp16(base + off,         g_xh + gx);
            cp16(base + 16384 + off, g_xl + gx);
            cp16(base + 32768 + off, WH + gw);
            cp16(base + 49152 + off, WL + gw);
        }
    };

    float s[16][4];
    #pragma unroll
    for (int g = 0; g < 16; g++)
        #pragma unroll
        for (int j = 0; j < 4; j++) s[g][j] = 0.0f;

    issue(0, 0);
    CP_COMMIT();

    for (int kt = 0; kt < 16; kt++) {
        if (kt) __syncthreads();            // buffer (kt+1)&1 free to overwrite
        if (kt < 15) issue(kt + 1, (kt + 1) & 1);
        CP_COMMIT();
        CP_WAIT1();
        __syncthreads();

        const uint32_t base = sb + (uint32_t)(kt & 1) * 65536;
        uint32_t ah[4][4], al[4][4];
        const int rA = (wid << 4) + (lane & 7) + ((lane >> 3) & 1) * 8;
        #pragma unroll
        for (int ks = 0; ks < 4; ks++) {
            const int ch = ks * 2 + (lane >> 4);
            ldsm_x4(ah[ks], swz_addr(base,         rA, ch));
            ldsm_x4(al[ks], swz_addr(base + 16384, rA, ch));
        }
        #pragma unroll
        for (int nf = 0; nf < 8; nf++) {
            const int rB = nf * 16 + (lane & 7) + (lane >> 4) * 8;
            #pragma unroll
            for (int ks = 0; ks < 4; ks++) {
                const int ch = ks * 2 + ((lane >> 3) & 1);
                uint32_t wh4[4], wl4[4];
                ldsm_x4(wh4, swz_addr(base + 32768, rB, ch));
                ldsm_x4(wl4, swz_addr(base + 49152, rB, ch));
                mma_bf16(s[2*nf],   ah[ks], wh4[0], wh4[1]);
                mma_bf16(s[2*nf+1], ah[ks], wh4[2], wh4[3]);
                mma_bf16(s[2*nf],   ah[ks], wl4[0], wl4[1]);
                mma_bf16(s[2*nf+1], ah[ks], wl4[2], wl4[3]);
                mma_bf16(s[2*nf],   al[ks], wh4[0], wh4[1]);
                mma_bf16(s[2*nf+1], al[ks], wh4[2], wh4[3]);
            }
        }
    }

    // epilogue: + bias, split to hi/lo, store head-split
    const int r1 = row0 + (wid << 4) + (lane >> 2);
    const int r2 = r1 + 8;
    const int bb1 = r1 >> 11, ss1 = r1 & (SEQ - 1);
    const int bb2 = r2 >> 11, ss2 = r2 & (SEQ - 1);
    #pragma unroll
    for (int g = 0; g < 16; g++) {
        const int c = col0 + g * 8 + (lane & 3) * 2;
        const int h = c >> 6, d = c & 63;
        float2 b2 = *(const float2*)(bvec + c);
        uint32_t hi, lo;
        split2(s[g][0] + b2.x, s[g][1] + b2.y, hi, lo);
        const size_t e1 = (((size_t)bb1 * NH + h) * SEQ + ss1) * HD + d;
        *(uint32_t*)&ohi[e1] = hi; *(uint32_t*)&olo[e1] = lo;
        split2(s[g][2] + b2.x, s[g][3] + b2.y, hi, lo);
        const size_t e2 = (((size_t)bb2 * NH + h) * SEQ + ss2) * HD + d;
        *(uint32_t*)&ohi[e2] = hi; *(uint32_t*)&olo[e2] = lo;
    }
}

// ---------------------------------------------------------------------------
// Kernel 2: HMMA attention, bf16x3, cp.async double-buffered K/V tiles.
// CTA = 128 q-rows x one (b,h); 8 warps; warp owns 16 q-rows x 128 k-cols.
// ---------------------------------------------------------------------------
#define SM_QH 0
#define SM_QL 16384
#define SM_TILES 32768                     // + buf*65536: KH,KL,VH,VL @16KB
#define ATTN_SMEM_BYTES (32768 + 131072)

__global__ __launch_bounds__(256, 1) void attn_mma_kernel(
    const float* __restrict__ bias,
    const int*   __restrict__ mask,
    float* __restrict__ outp,
    float* __restrict__ attn)
{
    extern __shared__ char smem[];
    const uint32_t sb = smem_u32(smem);

    const int tid = threadIdx.x;
    const int wid = tid >> 5, lane = tid & 31;
    const int bh = blockIdx.y;
    const int h  = bh & (NH - 1);
    const int q0 = blockIdx.x << 7;
    const float scale = 0.125f;
    const size_t bhbase = (size_t)bh * SEQ;

    auto issue_kv = [&](int kt, int buf) {
        const int k0 = kt << 7;
        const uint32_t base = sb + SM_TILES + (uint32_t)buf * 65536;
        const char* kh = (const char*)(g_k_hi + (bhbase + k0) * HD);
        const char* kl = (const char*)(g_k_lo + (bhbase + k0) * HD);
        const char* vh = (const char*)(g_v_hi + (bhbase + k0) * HD);
        const char* vl = (const char*)(g_v_lo + (bhbase + k0) * HD);
        #pragma unroll
        for (int it = 0; it < 4; it++) {
            const int idx = tid + it * 256;
            const uint32_t off = (uint32_t)(idx << 4);
            const uint32_t dst = off ^ ((off >> 3) & 0x70);
            cp16(base + dst,         kh + off);
            cp16(base + 16384 + dst, kl + off);
            cp16(base + 32768 + dst, vh + off);
            cp16(base + 49152 + dst, vl + off);
        }
    };

    // prologue: Q tiles + K/V(0), one cp.async group
    {
        const char* qh = (const char*)(g_q_hi + (bhbase + q0) * HD);
        const char* ql = (const char*)(g_q_lo + (bhbase + q0) * HD);
        #pragma unroll
        for (int it = 0; it < 4; it++) {
            const int idx = tid + it * 256;
            const uint32_t off = (uint32_t)(idx << 4);
            const uint32_t dst = off ^ ((off >> 3) & 0x70);
            cp16(sb + SM_QH + dst, qh + off);
            cp16(sb + SM_QL + dst, ql + off);
        }
    }
    issue_kv(0, 0);
    CP_COMMIT();

    uint32_t qfh[4][4], qfl[4][4];

    float o[8][4];
    #pragma unroll
    for (int g = 0; g < 8; g++)
        #pragma unroll
        for (int j = 0; j < 4; j++) o[g][j] = 0.0f;
    float rsum1 = 0.0f, rsum2 = 0.0f;

    const int r1 = (wid << 4) + (lane >> 2);
    const int qg1 = q0 + r1, qg2 = qg1 + 8;
    const float* brow1 = bias + ((size_t)h * SEQ + qg1) * SEQ;
    const float* brow2 = bias + ((size_t)h * SEQ + qg2) * SEQ;
    const int*   mrow1 = mask + (size_t)qg1 * SEQ;
    const int*   mrow2 = mask + (size_t)qg2 * SEQ;
    float*       arow1 = attn + (bhbase + qg1) * SEQ;
    float*       arow2 = attn + (bhbase + qg2) * SEQ;

    for (int kt = 0; kt < SEQ / 128; kt++) {
        const int k0 = kt << 7;
        if (kt) __syncthreads();            // buffer (kt+1)&1 free to overwrite
        if (kt < 15) issue_kv(kt + 1, (kt + 1) & 1);
        CP_COMMIT();
        CP_WAIT1();
        __syncthreads();

        if (kt == 0) {                      // hoist Q fragments once
            const int rA = (wid << 4) + (lane & 7) + ((lane >> 3) & 1) * 8;
            #pragma unroll
            for (int ks = 0; ks < 4; ks++) {
                const int ch = ks * 2 + (lane >> 4);
                ldsm_x4(qfh[ks], swz_addr(sb + SM_QH, rA, ch));
                ldsm_x4(qfl[ks], swz_addr(sb + SM_QL, rA, ch));
            }
        }
        const uint32_t base = sb + SM_TILES + (uint32_t)(kt & 1) * 65536;

        // ---- S = Q K^T over 128 cols (16 n8-groups), bf16x3 ----
        float s[16][4];
        #pragma unroll
        for (int g = 0; g < 16; g++)
            #pragma unroll
            for (int j = 0; j < 4; j++) s[g][j] = 0.0f;

        #pragma unroll
        for (int nf = 0; nf < 8; nf++) {
            const int rB = nf * 16 + (lane & 7) + (lane >> 4) * 8;
            #pragma unroll
            for (int ks = 0; ks < 4; ks++) {
                const int ch = ks * 2 + ((lane >> 3) & 1);
                uint32_t kh4[4], kl4[4];
                ldsm_x4(kh4, swz_addr(base,         rB, ch));
                ldsm_x4(kl4, swz_addr(base + 16384, rB, ch));
                mma_bf16(s[2*nf],   qfh[ks], kh4[0], kh4[1]);
                mma_bf16(s[2*nf+1], qfh[ks], kh4[2], kh4[3]);
                mma_bf16(s[2*nf],   qfh[ks], kl4[0], kl4[1]);
                mma_bf16(s[2*nf+1], qfh[ks], kl4[2], kl4[3]);
                mma_bf16(s[2*nf],   qfl[ks], kh4[0], kh4[1]);
                mma_bf16(s[2*nf+1], qfl[ks], kh4[2], kh4[3]);
            }
        }

        // ---- register epilogue: bias + mask + exp; attn store; pack P ----
        uint32_t ph[8][4], pl[8][4];
        #pragma unroll
        for (int g = 0; g < 16; g++) {
            const int c = k0 + g * 8 + (lane & 3) * 2;
            float2 bA = *(const float2*)(brow1 + c);
            float2 bB = *(const float2*)(brow2 + c);
            int2   mA = *(const int2*)(mrow1 + c);
            int2   mB = *(const int2*)(mrow2 + c);
            float p0 = mA.x ? __expf(fmaf(s[g][0], scale, bA.x)) : 0.0f;
            float p1 = mA.y ? __expf(fmaf(s[g][1], scale, bA.y)) : 0.0f;
            float p2 = mB.x ? __expf(fmaf(s[g][2], scale, bB.x)) : 0.0f;
            float p3 = mB.y ? __expf(fmaf(s[g][3], scale, bB.y)) : 0.0f;
            rsum1 += p0 + p1;
            rsum2 += p2 + p3;
            *(float2*)(arow1 + c) = make_float2(p0, p1);
            *(float2*)(arow2 + c) = make_float2(p2, p3);
            const int ks = g >> 1, ix = (g & 1) * 2;
            split2(p0, p1, ph[ks][ix + 0], pl[ks][ix + 0]);
            split2(p2, p3, ph[ks][ix + 1], pl[ks][ix + 1]);
        }

        // ---- O += P V (bf16x3): B = V via ldmatrix.trans ----
        #pragma unroll
        for (int ks = 0; ks < 8; ks++) {
            const int rV = ks * 16 + (lane & 7) + ((lane >> 3) & 1) * 8;
            #pragma unroll
            for (int dg = 0; dg < 4; dg++) {
                const int ch = 2 * dg + (lane >> 4);
                uint32_t vh4[4], vl4[4];
                ldsm_x4t(vh4, swz_addr(base + 32768, rV, ch));
                ldsm_x4t(vl4, swz_addr(base + 49152, rV, ch));
                mma_bf16(o[2*dg],   ph[ks], vh4[0], vh4[1]);
                mma_bf16(o[2*dg+1], ph[ks], vh4[2], vh4[3]);
                mma_bf16(o[2*dg],   ph[ks], vl4[0], vl4[1]);
                mma_bf16(o[2*dg+1], ph[ks], vl4[2], vl4[3]);
                mma_bf16(o[2*dg],   pl[ks], vh4[0], vh4[1]);
                mma_bf16(o[2*dg+1], pl[ks], vh4[2], vh4[3]);
            }
        }
    }

    // ---- rowsum quad-reduce ----
    rsum1 += __shfl_xor_sync(0xffffffffu, rsum1, 1);
    rsum1 += __shfl_xor_sync(0xffffffffu, rsum1, 2);
    rsum2 += __shfl_xor_sync(0xffffffffu, rsum2, 1);
    rsum2 += __shfl_xor_sync(0xffffffffu, rsum2, 2);
    if ((lane & 3) == 0) {
        g_rowsum[bhbase + qg1] = rsum1;
        g_rowsum[bhbase + qg2] = rsum2;
    }
    const float inv1 = 1.0f / rsum1;
    const float inv2 = 1.0f / rsum2;

    float* or1 = outp + (bhbase + qg1) * HD;
    float* or2 = outp + (bhbase + qg2) * HD;
    #pragma unroll
    for (int g = 0; g < 8; g++) {
        const int c = g * 8 + (lane & 3) * 2;
        *(float2*)(or1 + c) = make_float2(o[g][0] * inv1, o[g][1] * inv1);
        *(float2*)(or2 + c) = make_float2(o[g][2] * inv2, o[g][3] * inv2);
    }
}

// ---------------------------------------------------------------------------
// Kernel 3: normalize attention weights by rowsum. One block per row.
// ---------------------------------------------------------------------------
__global__ __launch_bounds__(512) void norm_kernel(float* __restrict__ attn)
{
    const size_t row = blockIdx.x;
    const float inv = 1.0f / g_rowsum[row];
    float4* p = (float4*)(attn + row * SEQ);
    float4 v = p[threadIdx.x];
    v.x *= inv; v.y *= inv; v.z *= inv; v.w *= inv;
    p[threadIdx.x] = v;
}

// ---------------------------------------------------------------------------
extern "C" void kernel_launch(void* const* d_in, const int* in_sizes, int n_in,
                              void* d_out, int out_size)
{
    const float* x    = (const float*)d_in[0];
    const float* bias = (const float*)d_in[1];
    const int*   mask = (const int*)d_in[2];
    const float* wq   = (const float*)d_in[3];
    const float* bq   = (const float*)d_in[4];
    const float* wk   = (const float*)d_in[5];
    const float* bk   = (const float*)d_in[6];
    const float* wv   = (const float*)d_in[7];
    const float* bv   = (const float*)d_in[8];

    float* outp = (float*)d_out;                       // [2,16,2048,64]
    float* attn = outp + (size_t)BH * SEQ * HD;        // [2,16,2048,2048]

    cudaFuncSetAttribute(qkv_hmma_kernel,
                         cudaFuncAttributeMaxDynamicSharedMemorySize,
                         QKV_SMEM_BYTES);
    cudaFuncSetAttribute(attn_mma_kernel,
                         cudaFuncAttributeMaxDynamicSharedMemorySize,
                         ATTN_SMEM_BYTES);

    // 0) split x / W into hi+lo bf16
    split_src_kernel<<<dim3(2048, 4), 256>>>(x, wq, wk, wv);

    // 1) QKV projections (HMMA bf16x3) -> split-bf16 Q/K/V
    qkv_hmma_kernel<<<dim3(DM / 128, (BSZ * SEQ) / 128, 3), 256,
                      QKV_SMEM_BYTES>>>(bq, bk, bv);

    // 2) HMMA fused attention
    attn_mma_kernel<<<dim3(SEQ / 128, BH), 256, ATTN_SMEM_BYTES>>>(
        bias, mask, outp, attn);

    // 3) normalize attention weights
    norm_kernel<<<dim3(BH * SEQ), 512>>>(attn);
}

// round 7
// speedup vs baseline: 2.0790x; 1.2995x over previous
#include <cuda_runtime.h>
#include <cuda_bf16.h>
#include <cstdint>

#define BSZ 2
#define NH 16
#define SEQ 2048
#define DM 1024
#define HD 64
#define BH (BSZ*NH)

// Scratch (device globals — no allocations allowed)
__device__ __nv_bfloat16 g_xh[BSZ*SEQ*DM];
__device__ __nv_bfloat16 g_xl[BSZ*SEQ*DM];
__device__ __nv_bfloat16 g_wh[3*DM*DM];
__device__ __nv_bfloat16 g_wl[3*DM*DM];
__device__ __nv_bfloat16 g_q_hi[BH * SEQ * HD];
__device__ __nv_bfloat16 g_q_lo[BH * SEQ * HD];
__device__ __nv_bfloat16 g_k_hi[BH * SEQ * HD];
__device__ __nv_bfloat16 g_k_lo[BH * SEQ * HD];
__device__ __nv_bfloat16 g_v_hi[BH * SEQ * HD];
__device__ __nv_bfloat16 g_v_lo[BH * SEQ * HD];

// ---- bf16 split: hi = bf16x2(a,b); lo = bf16x2 residual ---------------------
__device__ __forceinline__ void split2(float a, float b, uint32_t& hi, uint32_t& lo) {
    __nv_bfloat162 h = __floats2bfloat162_rn(a, b);
    float2 hf = __bfloat1622float2(h);
    __nv_bfloat162 l = __floats2bfloat162_rn(a - hf.x, b - hf.y);
    hi = *reinterpret_cast<uint32_t*>(&h);
    lo = *reinterpret_cast<uint32_t*>(&l);
}

// ---- smem / ldmatrix / mma / cp.async primitives ----------------------------
__device__ __forceinline__ uint32_t smem_u32(const void* p) {
    uint32_t a;
    asm("{ .reg .u64 t; cvta.to.shared.u64 t, %1; cvt.u32.u64 %0, t; }"
        : "=r"(a) : "l"(p));
    return a;
}
// 128B-row tiles: XOR 16B-chunk by (row&7)
__device__ __forceinline__ uint32_t swz_addr(uint32_t base, int row, int chunk) {
    uint32_t off = (uint32_t)(row * 128 + chunk * 16);
    return base + (off ^ ((off >> 3) & 0x70));
}
// 64B-row tiles: XOR 16B-chunk by (row&3)-ish (SW64)
__device__ __forceinline__ uint32_t swz64_addr(uint32_t base, int row, int chunk) {
    uint32_t off = (uint32_t)(row * 64 + chunk * 16);
    return base + (off ^ ((off >> 3) & 0x30));
}
__device__ __forceinline__ void ldsm_x4(uint32_t* r, uint32_t a) {
    asm volatile("ldmatrix.sync.aligned.m8n8.x4.shared.b16 {%0,%1,%2,%3}, [%4];"
        : "=r"(r[0]), "=r"(r[1]), "=r"(r[2]), "=r"(r[3]) : "r"(a));
}
__device__ __forceinline__ void ldsm_x4t(uint32_t* r, uint32_t a) {
    asm volatile("ldmatrix.sync.aligned.m8n8.x4.trans.shared.b16 {%0,%1,%2,%3}, [%4];"
        : "=r"(r[0]), "=r"(r[1]), "=r"(r[2]), "=r"(r[3]) : "r"(a));
}
__device__ __forceinline__ void mma_bf16(float* d, const uint32_t* a,
                                         uint32_t b0, uint32_t b1) {
    asm volatile("mma.sync.aligned.m16n8k16.row.col.f32.bf16.bf16.f32 "
        "{%0,%1,%2,%3}, {%4,%5,%6,%7}, {%8,%9}, {%0,%1,%2,%3};"
        : "+f"(d[0]), "+f"(d[1]), "+f"(d[2]), "+f"(d[3])
        : "r"(a[0]), "r"(a[1]), "r"(a[2]), "r"(a[3]), "r"(b0), "r"(b1));
}
__device__ __forceinline__ void cp16(uint32_t dst, const void* src) {
    asm volatile("cp.async.cg.shared.global [%0], [%1], 16;"
                 :: "r"(dst), "l"(src) : "memory");
}
#define CP_COMMIT() asm volatile("cp.async.commit_group;" ::: "memory")
#define CP_WAIT1()  asm volatile("cp.async.wait_group 1;" ::: "memory")

// ---------------------------------------------------------------------------
// Kernel 0: split fp32 sources into hi/lo bf16 buffers (x, wq, wk, wv).
// ---------------------------------------------------------------------------
__global__ __launch_bounds__(256) void split_src_kernel(
    const float* __restrict__ x,
    const float* __restrict__ wq, const float* __restrict__ wk,
    const float* __restrict__ wv)
{
    const int z = blockIdx.y;
    const float* src;
    uint32_t *oh, *ol;
    size_t n2;
    if (z == 0) {
        src = x; oh = (uint32_t*)g_xh; ol = (uint32_t*)g_xl;
        n2 = (size_t)BSZ * SEQ * DM / 2;
    } else {
        src = (z == 1) ? wq : (z == 2) ? wk : wv;
        oh = (uint32_t*)(g_wh + (size_t)(z - 1) * DM * DM);
        ol = (uint32_t*)(g_wl + (size_t)(z - 1) * DM * DM);
        n2 = (size_t)DM * DM / 2;
    }
    for (size_t i = (size_t)blockIdx.x * 256 + threadIdx.x; i < n2;
         i += (size_t)gridDim.x * 256) {
        float2 v = ((const float2*)src)[i];
        uint32_t hi, lo;
        split2(v.x, v.y, hi, lo);
        oh[i] = hi; ol[i] = lo;
    }
}

// ---------------------------------------------------------------------------
// Kernel 1: QKV projection via HMMA bf16x3. 128x128 tile, K-slab 32,
// 64B-row smem (SW64 swizzle), double-buffered, 2 CTAs/SM.
// ---------------------------------------------------------------------------
#define QKV_SMEM_BYTES 65536

__global__ __launch_bounds__(256, 2) void qkv_hmma_kernel(
    const float* __restrict__ bq, const float* __restrict__ bk,
    const float* __restrict__ bv)
{
    extern __shared__ char smem[];
    const uint32_t sb = smem_u32(smem);
    const int tid = threadIdx.x, wid = tid >> 5, lane = tid & 31;
    const int z = blockIdx.z;
    const float* bvec = (z == 0) ? bq : (z == 1) ? bk : bv;
    __nv_bfloat16* ohi = (z == 0) ? g_q_hi : (z == 1) ? g_k_hi : g_v_hi;
    __nv_bfloat16* olo = (z == 0) ? g_q_lo : (z == 1) ? g_k_lo : g_v_lo;
    const __nv_bfloat16* WH = g_wh + (size_t)z * DM * DM;
    const __nv_bfloat16* WL = g_wl + (size_t)z * DM * DM;
    const int col0 = blockIdx.x << 7;
    const int row0 = blockIdx.y << 7;

    auto issue = [&](int slab, int buf) {
        const int k0 = slab << 5;
        const uint32_t base = sb + (uint32_t)buf * 32768;
        #pragma unroll
        for (int it = 0; it < 2; it++) {
            const int idx = tid + it * 256;     // 0..511
            const int r = idx >> 2, c = idx & 3;
            uint32_t off = (uint32_t)(r * 64 + c * 16);
            off ^= (off >> 3) & 0x30;
            const size_t gx = (size_t)(row0 + r) * DM + k0 + c * 8;
            const size_t gw = (size_t)(col0 + r) * DM + k0 + c * 8;
            cp16(base + off,         g_xh + gx);
            cp16(base + 8192 + off,  g_xl + gx);
            cp16(base + 16384 + off, WH + gw);
            cp16(base + 24576 + off, WL + gw);
        }
    };

    float s[16][4];
    #pragma unroll
    for (int g = 0; g < 16; g++)
        #pragma unroll
        for (int j = 0; j < 4; j++) s[g][j] = 0.0f;

    issue(0, 0);
    CP_COMMIT();

    for (int kt = 0; kt < 32; kt++) {
        if (kt) __syncthreads();
        if (kt < 31) issue(kt + 1, (kt + 1) & 1);
        CP_COMMIT();
        CP_WAIT1();
        __syncthreads();

        const uint32_t base = sb + (uint32_t)(kt & 1) * 32768;
        const int rA = (wid << 4) + (lane & 7) + ((lane >> 3) & 1) * 8;
        uint32_t ah[2][4], al[2][4];
        #pragma unroll
        for (int ks = 0; ks < 2; ks++) {
            const int ch = ks * 2 + (lane >> 4);
            ldsm_x4(ah[ks], swz64_addr(base,        rA, ch));
            ldsm_x4(al[ks], swz64_addr(base + 8192, rA, ch));
        }
        #pragma unroll
        for (int nf = 0; nf < 8; nf++) {
            const int rB = nf * 16 + (lane & 7) + (lane >> 4) * 8;
            #pragma unroll
            for (int ks = 0; ks < 2; ks++) {
                const int ch = ks * 2 + ((lane >> 3) & 1);
                uint32_t wh4[4], wl4[4];
                ldsm_x4(wh4, swz64_addr(base + 16384, rB, ch));
                ldsm_x4(wl4, swz64_addr(base + 24576, rB, ch));
                mma_bf16(s[2*nf],   ah[ks], wh4[0], wh4[1]);
                mma_bf16(s[2*nf+1], ah[ks], wh4[2], wh4[3]);
                mma_bf16(s[2*nf],   ah[ks], wl4[0], wl4[1]);
                mma_bf16(s[2*nf+1], ah[ks], wl4[2], wl4[3]);
                mma_bf16(s[2*nf],   al[ks], wh4[0], wh4[1]);
                mma_bf16(s[2*nf+1], al[ks], wh4[2], wh4[3]);
            }
        }
    }

    // epilogue: + bias, split to hi/lo, store head-split
    const int r1 = row0 + (wid << 4) + (lane >> 2);
    const int r2 = r1 + 8;
    const int bb1 = r1 >> 11, ss1 = r1 & (SEQ - 1);
    const int bb2 = r2 >> 11, ss2 = r2 & (SEQ - 1);
    #pragma unroll
    for (int g = 0; g < 16; g++) {
        const int c = col0 + g * 8 + (lane & 3) * 2;
        const int h = c >> 6, d = c & 63;
        float2 b2 = *(const float2*)(bvec + c);
        uint32_t hi, lo;
        split2(s[g][0] + b2.x, s[g][1] + b2.y, hi, lo);
        const size_t e1 = (((size_t)bb1 * NH + h) * SEQ + ss1) * HD + d;
        *(uint32_t*)&ohi[e1] = hi; *(uint32_t*)&olo[e1] = lo;
        split2(s[g][2] + b2.x, s[g][3] + b2.y, hi, lo);
        const size_t e2 = (((size_t)bb2 * NH + h) * SEQ + ss2) * HD + d;
        *(uint32_t*)&ohi[e2] = hi; *(uint32_t*)&olo[e2] = lo;
    }
}

// ---------------------------------------------------------------------------
// Kernel 2: HMMA attention, bf16x3, 64-wide k-tiles, 2 CTAs/SM,
// fused attn rescale (no separate norm pass).
// ---------------------------------------------------------------------------
#define SM_QH 0
#define SM_QL 16384
#define SM_TILES 32768                 // + buf*32768: KH+0, KL+8K, VH+16K, VL+24K
#define ATTN_SMEM_BYTES 98304

__global__ __launch_bounds__(256, 2) void attn_mma_kernel(
    const float* __restrict__ bias,
    const int*   __restrict__ mask,
    float* __restrict__ outp,
    float* __restrict__ attn)
{
    extern __shared__ char smem[];
    const uint32_t sb = smem_u32(smem);

    const int tid = threadIdx.x;
    const int wid = tid >> 5, lane = tid & 31;
    const int bh = blockIdx.y;
    const int h  = bh & (NH - 1);
    const int q0 = blockIdx.x << 7;
    const float scale = 0.125f;
    const size_t bhbase = (size_t)bh * SEQ;

    auto issue_kv = [&](int kt, int buf) {
        const int k0 = kt << 6;
        const uint32_t base = sb + SM_TILES + (uint32_t)buf * 32768;
        const char* kh = (const char*)(g_k_hi + (bhbase + k0) * HD);
        const char* kl = (const char*)(g_k_lo + (bhbase + k0) * HD);
        const char* vh = (const char*)(g_v_hi + (bhbase + k0) * HD);
        const char* vl = (const char*)(g_v_lo + (bhbase + k0) * HD);
        #pragma unroll
        for (int it = 0; it < 2; it++) {
            const int idx = tid + it * 256;     // 0..511
            const uint32_t off = (uint32_t)(idx << 4);
            const uint32_t dst = off ^ ((off >> 3) & 0x70);
            cp16(base + dst,         kh + off);
            cp16(base + 8192 + dst,  kl + off);
            cp16(base + 16384 + dst, vh + off);
            cp16(base + 24576 + dst, vl + off);
        }
    };

    // prologue: Q tiles + K/V(0)
    {
        const char* qh = (const char*)(g_q_hi + (bhbase + q0) * HD);
        const char* ql = (const char*)(g_q_lo + (bhbase + q0) * HD);
        #pragma unroll
        for (int it = 0; it < 4; it++) {
            const int idx = tid + it * 256;     // 0..1023
            const uint32_t off = (uint32_t)(idx << 4);
            const uint32_t dst = off ^ ((off >> 3) & 0x70);
            cp16(sb + SM_QH + dst, qh + off);
            cp16(sb + SM_QL + dst, ql + off);
        }
    }
    issue_kv(0, 0);
    CP_COMMIT();

    float o[8][4];
    #pragma unroll
    for (int g = 0; g < 8; g++)
        #pragma unroll
        for (int j = 0; j < 4; j++) o[g][j] = 0.0f;
    float rsum1 = 0.0f, rsum2 = 0.0f;

    const int r1 = (wid << 4) + (lane >> 2);
    const int qg1 = q0 + r1, qg2 = qg1 + 8;
    const float* brow1 = bias + ((size_t)h * SEQ + qg1) * SEQ;
    const float* brow2 = bias + ((size_t)h * SEQ + qg2) * SEQ;
    const int*   mrow1 = mask + (size_t)qg1 * SEQ;
    const int*   mrow2 = mask + (size_t)qg2 * SEQ;
    float*       arow1 = attn + (bhbase + qg1) * SEQ;
    float*       arow2 = attn + (bhbase + qg2) * SEQ;

    const int rA = (wid << 4) + (lane & 7) + ((lane >> 3) & 1) * 8;

    for (int kt = 0; kt < SEQ / 64; kt++) {
        const int k0 = kt << 6;
        if (kt) __syncthreads();
        if (kt < SEQ / 64 - 1) issue_kv(kt + 1, (kt + 1) & 1);
        CP_COMMIT();
        CP_WAIT1();
        __syncthreads();

        const uint32_t base = sb + SM_TILES + (uint32_t)(kt & 1) * 32768;

        // ---- S = Q K^T over 64 cols (8 n8-groups), bf16x3 ----
        float s[8][4];
        #pragma unroll
        for (int g = 0; g < 8; g++)
            #pragma unroll
            for (int j = 0; j < 4; j++) s[g][j] = 0.0f;

        #pragma unroll
        for (int ks = 0; ks < 4; ks++) {
            uint32_t qfh[4], qfl[4];
            const int chA = ks * 2 + (lane >> 4);
            ldsm_x4(qfh, swz_addr(sb + SM_QH, rA, chA));
            ldsm_x4(qfl, swz_addr(sb + SM_QL, rA, chA));
            #pragma unroll
            for (int nf = 0; nf < 4; nf++) {
                const int rB = nf * 16 + (lane & 7) + (lane >> 4) * 8;
                const int ch = ks * 2 + ((lane >> 3) & 1);
                uint32_t kh4[4], kl4[4];
                ldsm_x4(kh4, swz_addr(base,        rB, ch));
                ldsm_x4(kl4, swz_addr(base + 8192, rB, ch));
                mma_bf16(s[2*nf],   qfh, kh4[0], kh4[1]);
                mma_bf16(s[2*nf+1], qfh, kh4[2], kh4[3]);
                mma_bf16(s[2*nf],   qfh, kl4[0], kl4[1]);
                mma_bf16(s[2*nf+1], qfh, kl4[2], kl4[3]);
                mma_bf16(s[2*nf],   qfl, kh4[0], kh4[1]);
                mma_bf16(s[2*nf+1], qfl, kh4[2], kh4[3]);
            }
        }

        // ---- register epilogue: bias + mask + exp; attn store; pack P ----
        uint32_t ph[4][4], pl[4][4];
        #pragma unroll
        for (int g = 0; g < 8; g++) {
            const int c = k0 + g * 8 + (lane & 3) * 2;
            float2 bA = *(const float2*)(brow1 + c);
            float2 bB = *(const float2*)(brow2 + c);
            int2   mA = *(const int2*)(mrow1 + c);
            int2   mB = *(const int2*)(mrow2 + c);
            float p0 = mA.x ? __expf(fmaf(s[g][0], scale, bA.x)) : 0.0f;
            float p1 = mA.y ? __expf(fmaf(s[g][1], scale, bA.y)) : 0.0f;
            float p2 = mB.x ? __expf(fmaf(s[g][2], scale, bB.x)) : 0.0f;
            float p3 = mB.y ? __expf(fmaf(s[g][3], scale, bB.y)) : 0.0f;
            rsum1 += p0 + p1;
            rsum2 += p2 + p3;
            *(float2*)(arow1 + c) = make_float2(p0, p1);
            *(float2*)(arow2 + c) = make_float2(p2, p3);
            const int ks = g >> 1, ix = (g & 1) * 2;
            split2(p0, p1, ph[ks][ix + 0], pl[ks][ix + 0]);
            split2(p2, p3, ph[ks][ix + 1], pl[ks][ix + 1]);
        }

        // ---- O += P V (bf16x3): B = V via ldmatrix.trans ----
        #pragma unroll
        for (int ks = 0; ks < 4; ks++) {
            const int rV = ks * 16 + (lane & 7) + ((lane >> 3) & 1) * 8;
            #pragma unroll
            for (int dg = 0; dg < 4; dg++) {
                const int ch = 2 * dg + (lane >> 4);
                uint32_t vh4[4], vl4[4];
                ldsm_x4t(vh4, swz_addr(base + 16384, rV, ch));
                ldsm_x4t(vl4, swz_addr(base + 24576, rV, ch));
                mma_bf16(o[2*dg],   ph[ks], vh4[0], vh4[1]);
                mma_bf16(o[2*dg+1], ph[ks], vh4[2], vh4[3]);
                mma_bf16(o[2*dg],   ph[ks], vl4[0], vl4[1]);
                mma_bf16(o[2*dg+1], ph[ks], vl4[2], vl4[3]);
                mma_bf16(o[2*dg],   pl[ks], vh4[0], vh4[1]);
                mma_bf16(o[2*dg+1], pl[ks], vh4[2], vh4[3]);
            }
        }
    }

    // ---- rowsum quad-reduce ----
    rsum1 += __shfl_xor_sync(0xffffffffu, rsum1, 1);
    rsum1 += __shfl_xor_sync(0xffffffffu, rsum1, 2);
    rsum2 += __shfl_xor_sync(0xffffffffu, rsum2, 1);
    rsum2 += __shfl_xor_sync(0xffffffffu, rsum2, 2);
    const float inv1 = 1.0f / rsum1;
    const float inv2 = 1.0f / rsum2;

    // normalized O
    float* or1 = outp + (bhbase + qg1) * HD;
    float* or2 = outp + (bhbase + qg2) * HD;
    #pragma unroll
    for (int g = 0; g < 8; g++) {
        const int c = g * 8 + (lane & 3) * 2;
        *(float2*)(or1 + c) = make_float2(o[g][0] * inv1, o[g][1] * inv1);
        *(float2*)(or2 + c) = make_float2(o[g][2] * inv2, o[g][3] * inv2);
    }

    // ---- fused attn rescale: warp rescales its own 16 rows ----
    float* rs = (float*)smem;          // 128 floats; KV smem no longer needed
    __syncthreads();                   // all attn stores done; smem free
    if ((lane & 3) == 0) {
        rs[r1] = inv1;
        rs[qg2 - q0] = inv2;
    }
    __syncthreads();
    #pragma unroll 1
    for (int rr = 0; rr < 16; rr++) {
        const int qr = (wid << 4) + rr;
        const float inv = rs[qr];
        float4* row = (float4*)(attn + (bhbase + q0 + qr) * SEQ);
        #pragma unroll 4
        for (int c = lane; c < SEQ / 4; c += 32) {
            float4 v = row[c];
            v.x *= inv; v.y *= inv; v.z *= inv; v.w *= inv;
            row[c] = v;
        }
    }
}

// ---------------------------------------------------------------------------
extern "C" void kernel_launch(void* const* d_in, const int* in_sizes, int n_in,
                              void* d_out, int out_size)
{
    const float* x    = (const float*)d_in[0];
    const float* bias = (const float*)d_in[1];
    const int*   mask = (const int*)d_in[2];
    const float* wq   = (const float*)d_in[3];
    const float* bq   = (const float*)d_in[4];
    const float* wk   = (const float*)d_in[5];
    const float* bk   = (const float*)d_in[6];
    const float* wv   = (const float*)d_in[7];
    const float* bv   = (const float*)d_in[8];

    float* outp = (float*)d_out;                       // [2,16,2048,64]
    float* attn = outp + (size_t)BH * SEQ * HD;        // [2,16,2048,2048]

    cudaFuncSetAttribute(qkv_hmma_kernel,
                         cudaFuncAttributeMaxDynamicSharedMemorySize,
                         QKV_SMEM_BYTES);
    cudaFuncSetAttribute(attn_mma_kernel,
                         cudaFuncAttributeMaxDynamicSharedMemorySize,
                         ATTN_SMEM_BYTES);

    // 0) split x / W into hi+lo bf16
    split_src_kernel<<<dim3(2048, 4), 256>>>(x, wq, wk, wv);

    // 1) QKV projections (HMMA bf16x3) -> split-bf16 Q/K/V
    qkv_hmma_kernel<<<dim3(DM / 128, (BSZ * SEQ) / 128, 3), 256,
                      QKV_SMEM_BYTES>>>(bq, bk, bv);

    // 2) HMMA fused attention + fused rescale
    attn_mma_kernel<<<dim3(SEQ / 128, BH), 256, ATTN_SMEM_BYTES>>>(
        bias, mask, outp, attn);
}